// round 1
// baseline (speedup 1.0000x reference)
#include <cuda_runtime.h>
#include <cuda_bf16.h>
#include <math.h>

// Problem constants
#define BB_   32
#define DIM_  256
#define HEADS_ 8
#define KD_   16       // KEY_DIM
#define DV_   64       // D = RATIO*KEY_DIM
#define NHKD_ 128      // KEY_DIM*HEADS
#define DH_   512      // D*HEADS
#define QKVO_ 768      // DH + 2*NH_KD
#define HH_   28
#define WW_   28
#define NN_   784      // H*W
#define EPSBN 1e-5f
#define SCALE_ 0.25f   // KEY_DIM^-0.5

// ---------------- scratch (device globals; no allocation) ----------------
__device__ float g_qkv[(size_t)BB_ * QKVO_ * NN_];   // [B,768,784]  (~77MB)
__device__ float g_qdw[(size_t)BB_ * NHKD_ * NN_];   // [B,128,784]  (~13MB)
__device__ float g_att[(size_t)BB_ * DH_ * NN_];     // [B,512,784]  (~51MB)

// =====================================================================
// Generic fp32 GEMM + BN epilogue.
//   C[z,m,n] = bn( sum_k A[m,k] * f(B[z,k,n]) )   f = relu if RELU_IN
// Block tile 64(M) x 128(N) x 16(K), 256 threads, 4x8 per thread.
// =====================================================================
template<bool RELU_IN>
__global__ void __launch_bounds__(256) gemm_bn_kernel(
    const float* __restrict__ A,      // [M,K]
    const float* __restrict__ Bbase,  // [Z,K,N]
    float*       __restrict__ Cbase,  // [Z,M,N]
    const float* __restrict__ gg, const float* __restrict__ bb,
    const float* __restrict__ mm, const float* __restrict__ vv,
    int M, int N, int K)
{
    const int m0 = blockIdx.x * 64;
    const int n0 = blockIdx.y * 128;
    const int z  = blockIdx.z;
    const float* Bm = Bbase + (size_t)z * K * N;
    float*       C  = Cbase + (size_t)z * M * N;

    __shared__ float As[16][68];
    __shared__ float Bs[16][132];

    const int t  = threadIdx.x;
    const int ty = t >> 4;          // 0..15 -> M rows ty*4..+3
    const int tx = t & 15;          // 0..15 -> N cols tx*4..+3 and 64+tx*4..+3

    float acc[4][8];
    #pragma unroll
    for (int i = 0; i < 4; ++i)
        #pragma unroll
        for (int j = 0; j < 8; ++j) acc[i][j] = 0.f;

    const int nkt = K >> 4;
    const int amr = t >> 2;         // 0..63 (A tile row)
    const int akq = (t & 3) * 4;    // 0,4,8,12 (A k quad)
    const int bkk = t >> 4;         // 0..15 (B tile k row)
    const int bnq = (t & 15) * 4;   // 0..60

    for (int kt = 0; kt < nkt; ++kt) {
        const int k0 = kt << 4;
        // stage loads in registers
        float4 a4 = *reinterpret_cast<const float4*>(&A[(size_t)(m0 + amr) * K + k0 + akq]);
        const float* Brow = &Bm[(size_t)(k0 + bkk) * N];
        const int c0 = n0 + bnq;
        const int c1 = n0 + 64 + bnq;
        float4 b0 = make_float4(0.f, 0.f, 0.f, 0.f);
        float4 b1 = make_float4(0.f, 0.f, 0.f, 0.f);
        if (c0 < N) b0 = *reinterpret_cast<const float4*>(&Brow[c0]);
        if (c1 < N) b1 = *reinterpret_cast<const float4*>(&Brow[c1]);
        if (RELU_IN) {
            b0.x = fmaxf(b0.x, 0.f); b0.y = fmaxf(b0.y, 0.f);
            b0.z = fmaxf(b0.z, 0.f); b0.w = fmaxf(b0.w, 0.f);
            b1.x = fmaxf(b1.x, 0.f); b1.y = fmaxf(b1.y, 0.f);
            b1.z = fmaxf(b1.z, 0.f); b1.w = fmaxf(b1.w, 0.f);
        }
        __syncthreads();
        As[akq + 0][amr] = a4.x; As[akq + 1][amr] = a4.y;
        As[akq + 2][amr] = a4.z; As[akq + 3][amr] = a4.w;
        *reinterpret_cast<float4*>(&Bs[bkk][bnq])      = b0;
        *reinterpret_cast<float4*>(&Bs[bkk][64 + bnq]) = b1;
        __syncthreads();

        #pragma unroll
        for (int kk = 0; kk < 16; ++kk) {
            float4 av  = *reinterpret_cast<const float4*>(&As[kk][ty * 4]);
            float4 bva = *reinterpret_cast<const float4*>(&Bs[kk][tx * 4]);
            float4 bvb = *reinterpret_cast<const float4*>(&Bs[kk][64 + tx * 4]);
            float am[4] = {av.x, av.y, av.z, av.w};
            float bn8[8] = {bva.x, bva.y, bva.z, bva.w, bvb.x, bvb.y, bvb.z, bvb.w};
            #pragma unroll
            for (int i = 0; i < 4; ++i)
                #pragma unroll
                for (int j = 0; j < 8; ++j)
                    acc[i][j] = fmaf(am[i], bn8[j], acc[i][j]);
        }
    }

    // BN epilogue
    #pragma unroll
    for (int i = 0; i < 4; ++i) {
        const int m = m0 + ty * 4 + i;
        const float s  = gg[m] * rsqrtf(vv[m] + EPSBN);
        const float tt = bb[m] - mm[m] * s;
        float* Crow = &C[(size_t)m * N];
        const int ca = n0 + tx * 4;
        const int cb = n0 + 64 + tx * 4;
        if (ca < N) {
            float4 o = make_float4(acc[i][0] * s + tt, acc[i][1] * s + tt,
                                   acc[i][2] * s + tt, acc[i][3] * s + tt);
            *reinterpret_cast<float4*>(&Crow[ca]) = o;
        }
        if (cb < N) {
            float4 o = make_float4(acc[i][4] * s + tt, acc[i][5] * s + tt,
                                   acc[i][6] * s + tt, acc[i][7] * s + tt);
            *reinterpret_cast<float4*>(&Crow[cb]) = o;
        }
    }
}

// =====================================================================
// Depthwise 3x3 conv (SAME, zero pad) + BN on q channels (first 128 of qkv)
// One block per (b, c) plane.
// =====================================================================
__global__ void __launch_bounds__(256) dwconv_kernel(
    const float* __restrict__ dw_w,
    const float* __restrict__ gg, const float* __restrict__ bb,
    const float* __restrict__ mm, const float* __restrict__ vv)
{
    const int bc = blockIdx.x;
    const int b  = bc >> 7;
    const int c  = bc & 127;
    const int t  = threadIdx.x;

    __shared__ float tile[30][30];
    for (int i = t; i < 900; i += 256) (&tile[0][0])[i] = 0.f;
    __syncthreads();

    const float* in = &g_qkv[((size_t)b * QKVO_ + c) * NN_];
    for (int n = t; n < NN_; n += 256)
        tile[n / WW_ + 1][n % WW_ + 1] = in[n];
    __syncthreads();

    float wv[9];
    #pragma unroll
    for (int k = 0; k < 9; ++k) wv[k] = dw_w[c * 9 + k];
    const float s  = gg[c] * rsqrtf(vv[c] + EPSBN);
    const float tt = bb[c] - mm[c] * s;

    float* outp = &g_qdw[((size_t)b * NHKD_ + c) * NN_];
    for (int n = t; n < NN_; n += 256) {
        const int y = n / WW_, x = n % WW_;
        float a = 0.f;
        #pragma unroll
        for (int ky = 0; ky < 3; ++ky)
            #pragma unroll
            for (int kx = 0; kx < 3; ++kx)
                a = fmaf(tile[y + ky][x + kx], wv[ky * 3 + kx], a);
        outp[n] = a * s + tt;
    }
}

// =====================================================================
// Fused attention: per block (query tile of 64, head, batch).
// Flash-style online softmax; K/V chunks of 64 in smem; P staged in smem.
// Relative-position bias computed on the fly from ab[h, dy*28+dx].
// =====================================================================
__global__ void __launch_bounds__(256) attn_kernel(
    const float* __restrict__ ab)
{
    const int qt = blockIdx.x;      // 0..12
    const int h  = blockIdx.y;      // 0..7
    const int b  = blockIdx.z;      // 0..31
    const int q0 = qt * 64;
    const int t  = threadIdx.x;
    const int ty = t >> 4;          // query rows ty*4..+3
    const int tx = t & 15;          // key cols / value dims tx*4..+3

    __shared__ float Qs[16][64];
    __shared__ float Ks[16][64];
    __shared__ float Vs[64][68];    // [n_local][d]
    __shared__ float Ps[64][68];    // [q_local][n_local]; reused as out stage [d][m]
    __shared__ float biasS[784];

    for (int i = t; i < 784; i += 256) biasS[i] = ab[h * 784 + i];

    // load Q tile [16 d][64 m]
    {
        const int d  = t >> 4;
        const int mq = (t & 15) * 4;
        const float* qrow = &g_qdw[((size_t)b * NHKD_ + h * KD_ + d) * NN_];
        float4 v = make_float4(0.f, 0.f, 0.f, 0.f);
        if (q0 + mq < NN_) v = *reinterpret_cast<const float4*>(&qrow[q0 + mq]);
        *reinterpret_cast<float4*>(&Qs[d][mq]) = v;
    }

    int my[4], mx[4];
    #pragma unroll
    for (int i = 0; i < 4; ++i) {
        int m = q0 + ty * 4 + i; if (m > 783) m = 783;
        my[i] = m / WW_; mx[i] = m % WW_;
    }

    float Mrow[4], Lrow[4], O[4][4];
    #pragma unroll
    for (int i = 0; i < 4; ++i) {
        Mrow[i] = -1e30f; Lrow[i] = 0.f;
        #pragma unroll
        for (int j = 0; j < 4; ++j) O[i][j] = 0.f;
    }

    const float* krow0 = &g_qkv[((size_t)b * QKVO_ + NHKD_ + h * KD_) * NN_];
    const float* vrow0 = &g_qkv[((size_t)b * QKVO_ + 2 * NHKD_ + h * DV_) * NN_];

    for (int n0 = 0; n0 < NN_; n0 += 64) {
        __syncthreads();
        // K chunk [16 d][64 n]
        {
            const int d  = t >> 4;
            const int nq = (t & 15) * 4;
            float4 v = make_float4(0.f, 0.f, 0.f, 0.f);
            if (n0 + nq < NN_) v = *reinterpret_cast<const float4*>(&krow0[(size_t)d * NN_ + n0 + nq]);
            *reinterpret_cast<float4*>(&Ks[d][nq]) = v;
        }
        // V chunk transposed -> Vs[n_local][d]
        {
            const int nq = (t & 15) * 4;
            #pragma unroll
            for (int r = 0; r < 4; ++r) {
                const int d = (t >> 4) + r * 16;
                float4 v = make_float4(0.f, 0.f, 0.f, 0.f);
                if (n0 + nq < NN_) v = *reinterpret_cast<const float4*>(&vrow0[(size_t)d * NN_ + n0 + nq]);
                Vs[nq + 0][d] = v.x; Vs[nq + 1][d] = v.y;
                Vs[nq + 2][d] = v.z; Vs[nq + 3][d] = v.w;
            }
        }
        __syncthreads();

        // S = scale * Q^T K + bias
        float sv[4][4];
        #pragma unroll
        for (int i = 0; i < 4; ++i)
            #pragma unroll
            for (int j = 0; j < 4; ++j) sv[i][j] = 0.f;
        #pragma unroll
        for (int d = 0; d < 16; ++d) {
            float4 qv = *reinterpret_cast<const float4*>(&Qs[d][ty * 4]);
            float4 kv = *reinterpret_cast<const float4*>(&Ks[d][tx * 4]);
            float qm[4] = {qv.x, qv.y, qv.z, qv.w};
            float kn[4] = {kv.x, kv.y, kv.z, kv.w};
            #pragma unroll
            for (int i = 0; i < 4; ++i)
                #pragma unroll
                for (int j = 0; j < 4; ++j)
                    sv[i][j] = fmaf(qm[i], kn[j], sv[i][j]);
        }
        #pragma unroll
        for (int j = 0; j < 4; ++j) {
            const int n = n0 + tx * 4 + j;
            if (n < NN_) {
                const int ny = n / WW_, nx = n % WW_;
                #pragma unroll
                for (int i = 0; i < 4; ++i) {
                    const int dy = abs(my[i] - ny), dx = abs(mx[i] - nx);
                    sv[i][j] = sv[i][j] * SCALE_ + biasS[dy * WW_ + dx];
                }
            } else {
                #pragma unroll
                for (int i = 0; i < 4; ++i) sv[i][j] = -1e30f;
            }
        }

        // online softmax
        #pragma unroll
        for (int i = 0; i < 4; ++i) {
            float mx4 = fmaxf(fmaxf(sv[i][0], sv[i][1]), fmaxf(sv[i][2], sv[i][3]));
            #pragma unroll
            for (int k = 1; k < 16; k <<= 1)
                mx4 = fmaxf(mx4, __shfl_xor_sync(0xffffffffu, mx4, k));
            const float newM = fmaxf(Mrow[i], mx4);
            const float corr = __expf(Mrow[i] - newM);
            Mrow[i] = newM;
            float rs = 0.f;
            #pragma unroll
            for (int j = 0; j < 4; ++j) {
                const float p = __expf(sv[i][j] - newM);
                sv[i][j] = p;
                rs += p;
            }
            #pragma unroll
            for (int k = 1; k < 16; k <<= 1)
                rs += __shfl_xor_sync(0xffffffffu, rs, k);
            Lrow[i] = Lrow[i] * corr + rs;
            #pragma unroll
            for (int j = 0; j < 4; ++j) O[i][j] *= corr;
        }
        #pragma unroll
        for (int i = 0; i < 4; ++i)
            *reinterpret_cast<float4*>(&Ps[ty * 4 + i][tx * 4]) =
                make_float4(sv[i][0], sv[i][1], sv[i][2], sv[i][3]);
        __syncthreads();

        // O += P @ V  (O[q][d], d = tx*4..+3)
        #pragma unroll 8
        for (int j = 0; j < 64; ++j) {
            float4 vv4 = *reinterpret_cast<const float4*>(&Vs[j][tx * 4]);
            #pragma unroll
            for (int i = 0; i < 4; ++i) {
                const float p = Ps[ty * 4 + i][j];
                O[i][0] = fmaf(p, vv4.x, O[i][0]);
                O[i][1] = fmaf(p, vv4.y, O[i][1]);
                O[i][2] = fmaf(p, vv4.z, O[i][2]);
                O[i][3] = fmaf(p, vv4.w, O[i][3]);
            }
        }
    }

    // normalize + transpose-stage through Ps -> coalesced global writes
    __syncthreads();
    #pragma unroll
    for (int i = 0; i < 4; ++i) {
        const float inv = 1.f / Lrow[i];
        #pragma unroll
        for (int dd = 0; dd < 4; ++dd)
            Ps[tx * 4 + dd][ty * 4 + i] = O[i][dd] * inv;   // Ps[d][m_local]
    }
    __syncthreads();
    {
        const int mq = (t & 15) * 4;
        if (q0 + mq < NN_) {
            #pragma unroll
            for (int r = 0; r < 4; ++r) {
                const int d = (t >> 4) + r * 16;
                float4 v = *reinterpret_cast<const float4*>(&Ps[d][mq]);
                *reinterpret_cast<float4*>(
                    &g_att[((size_t)b * DH_ + h * DV_ + d) * NN_ + q0 + mq]) = v;
            }
        }
    }
}

// =====================================================================
// launch
// =====================================================================
extern "C" void kernel_launch(void* const* d_in, const int* in_sizes, int n_in,
                              void* d_out, int out_size)
{
    const float* x      = (const float*)d_in[0];
    const float* qkv_w  = (const float*)d_in[1];
    const float* qkv_g  = (const float*)d_in[2];
    const float* qkv_b  = (const float*)d_in[3];
    const float* qkv_m  = (const float*)d_in[4];
    const float* qkv_v  = (const float*)d_in[5];
    const float* dw_w   = (const float*)d_in[6];
    const float* dw_g   = (const float*)d_in[7];
    const float* dw_b   = (const float*)d_in[8];
    const float* dw_m   = (const float*)d_in[9];
    const float* dw_v   = (const float*)d_in[10];
    const float* ab     = (const float*)d_in[11];
    const float* proj_w = (const float*)d_in[12];
    const float* proj_g = (const float*)d_in[13];
    const float* proj_b = (const float*)d_in[14];
    const float* proj_m = (const float*)d_in[15];
    const float* proj_v = (const float*)d_in[16];
    float* out = (float*)d_out;

    void *p_qkv, *p_att;
    cudaGetSymbolAddress(&p_qkv, g_qkv);
    cudaGetSymbolAddress(&p_att, g_att);

    // 1) QKV 1x1 conv + BN  : per-batch GEMM [768,256]x[256,784]
    gemm_bn_kernel<false><<<dim3(QKVO_ / 64, (NN_ + 127) / 128, BB_), 256>>>(
        qkv_w, x, (float*)p_qkv, qkv_g, qkv_b, qkv_m, qkv_v,
        QKVO_, NN_, DIM_);

    // 2) depthwise 3x3 + BN on q channels
    dwconv_kernel<<<BB_ * NHKD_, 256>>>(dw_w, dw_g, dw_b, dw_m, dw_v);

    // 3) attention (flash-style, fused bias/softmax)
    attn_kernel<<<dim3((NN_ + 63) / 64, HEADS_, BB_), 256>>>(ab);

    // 4) relu + 1x1 proj + BN : per-batch GEMM [256,512]x[512,784]
    gemm_bn_kernel<true><<<dim3(DIM_ / 64, (NN_ + 127) / 128, BB_), 256>>>(
        proj_w, (const float*)p_att, out, proj_g, proj_b, proj_m, proj_v,
        DIM_, NN_, DH_);
}

// round 2
// speedup vs baseline: 1.7874x; 1.7874x over previous
#include <cuda_runtime.h>
#include <cuda_bf16.h>
#include <math.h>

// Problem constants
#define BB_   32
#define DIM_  256
#define HEADS_ 8
#define KD_   16
#define DV_   64
#define NHKD_ 128
#define DH_   512
#define QKVO_ 768
#define WW_   28
#define NN_   784
#define EPSBN 1e-5f
#define SCALE_ 0.25f

// ---------------- scratch (device globals; no allocation) ----------------
__device__ float g_qkv[(size_t)BB_ * QKVO_ * NN_];
__device__ float g_qdw[(size_t)BB_ * NHKD_ * NN_];
__device__ float g_att[(size_t)BB_ * DH_ * NN_];

// ---------------- tf32 helpers ----------------
__device__ __forceinline__ unsigned f2tf(float f) {
    unsigned u; asm("cvt.rna.tf32.f32 %0, %1;" : "=r"(u) : "f"(f)); return u;
}
__device__ __forceinline__ float f2tff(float f) {
    return __uint_as_float(f2tf(f));
}
__device__ __forceinline__ void mma8(float4& c, const unsigned a[4], const unsigned b[2]) {
    asm volatile(
        "mma.sync.aligned.m16n8k8.row.col.f32.tf32.tf32.f32 "
        "{%0,%1,%2,%3},{%4,%5,%6,%7},{%8,%9},{%0,%1,%2,%3};"
        : "+f"(c.x), "+f"(c.y), "+f"(c.z), "+f"(c.w)
        : "r"(a[0]), "r"(a[1]), "r"(a[2]), "r"(a[3]), "r"(b[0]), "r"(b[1]));
}

// =====================================================================
// tf32 GEMM + BN epilogue.  C[z,m,n] = bn( A[m,:] . f(B[z,:,n]) )
// Block tile 64(M) x 112(N) x 32(K); 4 warps, warp tile 32x56.
// Requires M%64==0, N%112==0, K%32==0. (768/256 x 784 x 256/512: all ok)
// =====================================================================
template<bool RELU_IN>
__global__ void __launch_bounds__(128) gemm_tf32(
    const float* __restrict__ A,
    const float* __restrict__ Bb,
    float*       __restrict__ Cb,
    const float* __restrict__ gg, const float* __restrict__ bbp,
    const float* __restrict__ mmp, const float* __restrict__ vvp,
    int M, int N, int K)
{
    const int m0 = blockIdx.x * 64;
    const int n0 = blockIdx.y * 112;
    const int z  = blockIdx.z;
    const float* Bz = Bb + (size_t)z * K * N;
    float*       C  = Cb + (size_t)z * M * N;

    __shared__ float As[64][36];
    __shared__ float Bs[32][116];

    const int t    = threadIdx.x;
    const int lane = t & 31, wid = t >> 5;
    const int g    = lane >> 2, tg = lane & 3;
    const int wm   = wid >> 1, wn = wid & 1;

    float4 acc[2][7];
    #pragma unroll
    for (int i = 0; i < 2; ++i)
        #pragma unroll
        for (int j = 0; j < 7; ++j) acc[i][j] = make_float4(0.f, 0.f, 0.f, 0.f);

    const int ar = t >> 1;         // A tile row 0..63
    const int ac = (t & 1) * 16;   // A col base
    const int br = t >> 2;         // B tile row 0..31
    const int bc = (t & 3) * 28;   // B col base

    for (int k0 = 0; k0 < K; k0 += 32) {
        float4 av[4], bv[7];
        const float* Arow = A + (size_t)(m0 + ar) * K + k0 + ac;
        #pragma unroll
        for (int i = 0; i < 4; ++i) av[i] = *reinterpret_cast<const float4*>(Arow + i * 4);
        const float* Brow = Bz + (size_t)(k0 + br) * N + n0 + bc;
        #pragma unroll
        for (int i = 0; i < 7; ++i) bv[i] = *reinterpret_cast<const float4*>(Brow + i * 4);
        if (RELU_IN) {
            #pragma unroll
            for (int i = 0; i < 7; ++i) {
                bv[i].x = fmaxf(bv[i].x, 0.f); bv[i].y = fmaxf(bv[i].y, 0.f);
                bv[i].z = fmaxf(bv[i].z, 0.f); bv[i].w = fmaxf(bv[i].w, 0.f);
            }
        }
        __syncthreads();
        #pragma unroll
        for (int i = 0; i < 4; ++i) {
            float* p = &As[ar][ac + i * 4];
            p[0] = f2tff(av[i].x); p[1] = f2tff(av[i].y);
            p[2] = f2tff(av[i].z); p[3] = f2tff(av[i].w);
        }
        #pragma unroll
        for (int i = 0; i < 7; ++i) {
            float* p = &Bs[br][bc + i * 4];
            p[0] = f2tff(bv[i].x); p[1] = f2tff(bv[i].y);
            p[2] = f2tff(bv[i].z); p[3] = f2tff(bv[i].w);
        }
        __syncthreads();

        #pragma unroll
        for (int ks = 0; ks < 4; ++ks) {
            const int kk = ks * 8;
            unsigned af[2][4], bf[7][2];
            #pragma unroll
            for (int mt = 0; mt < 2; ++mt) {
                const int mr = wm * 32 + mt * 16;
                af[mt][0] = __float_as_uint(As[mr + g][kk + tg]);
                af[mt][1] = __float_as_uint(As[mr + g + 8][kk + tg]);
                af[mt][2] = __float_as_uint(As[mr + g][kk + tg + 4]);
                af[mt][3] = __float_as_uint(As[mr + g + 8][kk + tg + 4]);
            }
            #pragma unroll
            for (int nt = 0; nt < 7; ++nt) {
                const int nc = wn * 56 + nt * 8 + g;
                bf[nt][0] = __float_as_uint(Bs[kk + tg][nc]);
                bf[nt][1] = __float_as_uint(Bs[kk + tg + 4][nc]);
            }
            #pragma unroll
            for (int mt = 0; mt < 2; ++mt)
                #pragma unroll
                for (int nt = 0; nt < 7; ++nt) mma8(acc[mt][nt], af[mt], bf[nt]);
        }
    }

    // BN epilogue
    #pragma unroll
    for (int mt = 0; mt < 2; ++mt) {
        const int r0 = m0 + wm * 32 + mt * 16 + g;
        const int r1 = r0 + 8;
        const float s0 = gg[r0] * rsqrtf(vvp[r0] + EPSBN);
        const float t0 = bbp[r0] - mmp[r0] * s0;
        const float s1 = gg[r1] * rsqrtf(vvp[r1] + EPSBN);
        const float t1 = bbp[r1] - mmp[r1] * s1;
        #pragma unroll
        for (int nt = 0; nt < 7; ++nt) {
            const int c = n0 + wn * 56 + nt * 8 + tg * 2;
            float4 a = acc[mt][nt];
            *reinterpret_cast<float2*>(&C[(size_t)r0 * N + c]) =
                make_float2(a.x * s0 + t0, a.y * s0 + t0);
            *reinterpret_cast<float2*>(&C[(size_t)r1 * N + c]) =
                make_float2(a.z * s1 + t1, a.w * s1 + t1);
        }
    }
}

// =====================================================================
// Depthwise 3x3 + BN (unchanged from round 1)
// =====================================================================
__global__ void __launch_bounds__(256) dwconv_kernel(
    const float* __restrict__ dw_w,
    const float* __restrict__ gg, const float* __restrict__ bb,
    const float* __restrict__ mm, const float* __restrict__ vv)
{
    const int bc = blockIdx.x;
    const int b  = bc >> 7;
    const int c  = bc & 127;
    const int t  = threadIdx.x;

    __shared__ float tile[30][30];
    for (int i = t; i < 900; i += 256) (&tile[0][0])[i] = 0.f;
    __syncthreads();

    const float* in = &g_qkv[((size_t)b * QKVO_ + c) * NN_];
    for (int n = t; n < NN_; n += 256)
        tile[n / WW_ + 1][n % WW_ + 1] = in[n];
    __syncthreads();

    float wv[9];
    #pragma unroll
    for (int k = 0; k < 9; ++k) wv[k] = dw_w[c * 9 + k];
    const float s  = gg[c] * rsqrtf(vv[c] + EPSBN);
    const float tt = bb[c] - mm[c] * s;

    float* outp = &g_qdw[((size_t)b * NHKD_ + c) * NN_];
    for (int n = t; n < NN_; n += 256) {
        const int y = n / WW_, x = n % WW_;
        float a = 0.f;
        #pragma unroll
        for (int ky = 0; ky < 3; ++ky)
            #pragma unroll
            for (int kx = 0; kx < 3; ++kx)
                a = fmaf(tile[y + ky][x + kx], wv[ky * 3 + kx], a);
        outp[n] = a * s + tt;
    }
}

// =====================================================================
// Flash attention with tf32 mma.
// Block: 64 queries, 4 warps (16 q each). Chunks of 64 keys.
// =====================================================================
__global__ void __launch_bounds__(128) attn_tf32(const float* __restrict__ ab)
{
    const int qt = blockIdx.x, h = blockIdx.y, b = blockIdx.z;
    const int q0 = qt * 64;
    const int t = threadIdx.x, lane = t & 31, wid = t >> 5;
    const int g = lane >> 2, tg = lane & 3;

    __shared__ float Qs[64][17];
    __shared__ float Ks[16][68];
    __shared__ float Vs[64][68];
    __shared__ float Ps[64][68];
    __shared__ float biasS[784];
    __shared__ int   nyS[64], nxS[64];

    for (int i = t; i < 784; i += 128) biasS[i] = ab[h * 784 + i];

    // Q [d][q] global -> Qs[q][d] (tf32)
    {
        const int d = t >> 3;
        const float* qrow = &g_qdw[((size_t)b * NHKD_ + h * KD_ + d) * NN_];
        #pragma unroll
        for (int r = 0; r < 2; ++r) {
            const int qq = ((t & 7) * 2 + r) * 4;
            float4 v = make_float4(0.f, 0.f, 0.f, 0.f);
            if (q0 + qq + 3 < NN_) v = *reinterpret_cast<const float4*>(&qrow[q0 + qq]);
            Qs[qq + 0][d] = f2tff(v.x); Qs[qq + 1][d] = f2tff(v.y);
            Qs[qq + 2][d] = f2tff(v.z); Qs[qq + 3][d] = f2tff(v.w);
        }
    }

    // per-thread query coords (2 rows)
    const int qr0 = q0 + wid * 16 + g;
    const int qc0 = qr0 < NN_ ? qr0 : NN_ - 1;
    const int qy0 = qc0 / WW_, qx0 = qc0 % WW_;
    const int qc1 = (qr0 + 8) < NN_ ? (qr0 + 8) : NN_ - 1;
    const int qy1 = qc1 / WW_, qx1 = qc1 % WW_;

    float M0 = -1e30f, M1 = -1e30f, L0 = 0.f, L1 = 0.f;
    float4 O[8];
    #pragma unroll
    for (int i = 0; i < 8; ++i) O[i] = make_float4(0.f, 0.f, 0.f, 0.f);

    const float* kbase = &g_qkv[((size_t)b * QKVO_ + NHKD_ + h * KD_) * NN_];
    const float* vbase = &g_qkv[((size_t)b * QKVO_ + 2 * NHKD_ + h * DV_) * NN_];
    const int mr = wid * 16;

    for (int n0 = 0; n0 < NN_; n0 += 64) {
        __syncthreads();
        // K chunk -> Ks[d][n]
        {
            const int d = t >> 3;
            const float* kr = kbase + (size_t)d * NN_;
            #pragma unroll
            for (int r = 0; r < 2; ++r) {
                const int nn = ((t & 7) * 2 + r) * 4;
                float4 v = make_float4(0.f, 0.f, 0.f, 0.f);
                if (n0 + nn + 3 < NN_) v = *reinterpret_cast<const float4*>(&kr[n0 + nn]);
                Ks[d][nn + 0] = f2tff(v.x); Ks[d][nn + 1] = f2tff(v.y);
                Ks[d][nn + 2] = f2tff(v.z); Ks[d][nn + 3] = f2tff(v.w);
            }
        }
        // V chunk -> Vs[n][d]
        {
            const int d = t >> 1;
            const float* vr = vbase + (size_t)d * NN_;
            #pragma unroll
            for (int r = 0; r < 8; ++r) {
                const int nn = ((t & 1) * 8 + r) * 4;
                float4 v = make_float4(0.f, 0.f, 0.f, 0.f);
                if (n0 + nn + 3 < NN_) v = *reinterpret_cast<const float4*>(&vr[n0 + nn]);
                Vs[nn + 0][d] = f2tff(v.x); Vs[nn + 1][d] = f2tff(v.y);
                Vs[nn + 2][d] = f2tff(v.z); Vs[nn + 3][d] = f2tff(v.w);
            }
        }
        if (t < 64) {
            int n = n0 + t; if (n > NN_ - 1) n = NN_ - 1;
            nyS[t] = n / WW_; nxS[t] = n % WW_;
        }
        __syncthreads();

        // ---- S = Q.K (16x64 per warp) ----
        float4 S[8];
        #pragma unroll
        for (int i = 0; i < 8; ++i) S[i] = make_float4(0.f, 0.f, 0.f, 0.f);
        #pragma unroll
        for (int ks = 0; ks < 2; ++ks) {
            const int kk = ks * 8;
            unsigned af[4];
            af[0] = __float_as_uint(Qs[mr + g][kk + tg]);
            af[1] = __float_as_uint(Qs[mr + g + 8][kk + tg]);
            af[2] = __float_as_uint(Qs[mr + g][kk + tg + 4]);
            af[3] = __float_as_uint(Qs[mr + g + 8][kk + tg + 4]);
            #pragma unroll
            for (int nt = 0; nt < 8; ++nt) {
                unsigned bf[2];
                bf[0] = __float_as_uint(Ks[kk + tg][nt * 8 + g]);
                bf[1] = __float_as_uint(Ks[kk + tg + 4][nt * 8 + g]);
                mma8(S[nt], af, bf);
            }
        }

        // ---- bias + mask ----
        #pragma unroll
        for (int nt = 0; nt < 8; ++nt) {
            const int c0 = nt * 8 + tg * 2;
            if (n0 + c0 < NN_) {
                const int ny = nyS[c0], nx = nxS[c0];
                S[nt].x = S[nt].x * SCALE_ + biasS[abs(qy0 - ny) * WW_ + abs(qx0 - nx)];
                S[nt].z = S[nt].z * SCALE_ + biasS[abs(qy1 - ny) * WW_ + abs(qx1 - nx)];
            } else { S[nt].x = -1e30f; S[nt].z = -1e30f; }
            if (n0 + c0 + 1 < NN_) {
                const int ny = nyS[c0 + 1], nx = nxS[c0 + 1];
                S[nt].y = S[nt].y * SCALE_ + biasS[abs(qy0 - ny) * WW_ + abs(qx0 - nx)];
                S[nt].w = S[nt].w * SCALE_ + biasS[abs(qy1 - ny) * WW_ + abs(qx1 - nx)];
            } else { S[nt].y = -1e30f; S[nt].w = -1e30f; }
        }

        // ---- online softmax (rows g and g+8) ----
        float mx0 = -1e30f, mx1 = -1e30f;
        #pragma unroll
        for (int nt = 0; nt < 8; ++nt) {
            mx0 = fmaxf(mx0, fmaxf(S[nt].x, S[nt].y));
            mx1 = fmaxf(mx1, fmaxf(S[nt].z, S[nt].w));
        }
        mx0 = fmaxf(mx0, __shfl_xor_sync(0xffffffffu, mx0, 1));
        mx0 = fmaxf(mx0, __shfl_xor_sync(0xffffffffu, mx0, 2));
        mx1 = fmaxf(mx1, __shfl_xor_sync(0xffffffffu, mx1, 1));
        mx1 = fmaxf(mx1, __shfl_xor_sync(0xffffffffu, mx1, 2));
        const float nM0 = fmaxf(M0, mx0), nM1 = fmaxf(M1, mx1);
        const float cor0 = __expf(M0 - nM0), cor1 = __expf(M1 - nM1);
        M0 = nM0; M1 = nM1;
        float rs0 = 0.f, rs1 = 0.f;
        #pragma unroll
        for (int nt = 0; nt < 8; ++nt) {
            S[nt].x = __expf(S[nt].x - nM0); rs0 += S[nt].x;
            S[nt].y = __expf(S[nt].y - nM0); rs0 += S[nt].y;
            S[nt].z = __expf(S[nt].z - nM1); rs1 += S[nt].z;
            S[nt].w = __expf(S[nt].w - nM1); rs1 += S[nt].w;
        }
        rs0 += __shfl_xor_sync(0xffffffffu, rs0, 1);
        rs0 += __shfl_xor_sync(0xffffffffu, rs0, 2);
        rs1 += __shfl_xor_sync(0xffffffffu, rs1, 1);
        rs1 += __shfl_xor_sync(0xffffffffu, rs1, 2);
        L0 = L0 * cor0 + rs0;
        L1 = L1 * cor1 + rs1;
        #pragma unroll
        for (int i = 0; i < 8; ++i) {
            O[i].x *= cor0; O[i].y *= cor0;
            O[i].z *= cor1; O[i].w *= cor1;
        }

        // ---- P to smem (tf32), per-warp private rows ----
        #pragma unroll
        for (int nt = 0; nt < 8; ++nt) {
            const int c = nt * 8 + tg * 2;
            Ps[mr + g][c]     = f2tff(S[nt].x);
            Ps[mr + g][c + 1] = f2tff(S[nt].y);
            Ps[mr + g + 8][c]     = f2tff(S[nt].z);
            Ps[mr + g + 8][c + 1] = f2tff(S[nt].w);
        }
        __syncwarp();

        // ---- O += P.V (16x64 per warp) ----
        #pragma unroll
        for (int ks = 0; ks < 8; ++ks) {
            const int kk = ks * 8;
            unsigned af[4];
            af[0] = __float_as_uint(Ps[mr + g][kk + tg]);
            af[1] = __float_as_uint(Ps[mr + g + 8][kk + tg]);
            af[2] = __float_as_uint(Ps[mr + g][kk + tg + 4]);
            af[3] = __float_as_uint(Ps[mr + g + 8][kk + tg + 4]);
            #pragma unroll
            for (int nt = 0; nt < 8; ++nt) {
                unsigned bf[2];
                bf[0] = __float_as_uint(Vs[kk + tg][nt * 8 + g]);
                bf[1] = __float_as_uint(Vs[kk + tg + 4][nt * 8 + g]);
                mma8(O[nt], af, bf);
            }
        }
    }

    // ---- normalize, transpose-stage, store ----
    __syncthreads();
    const float i0 = 1.f / L0, i1 = 1.f / L1;
    #pragma unroll
    for (int nt = 0; nt < 8; ++nt) {
        const int d = nt * 8 + tg * 2;
        Ps[d][mr + g]         = O[nt].x * i0;
        Ps[d + 1][mr + g]     = O[nt].y * i0;
        Ps[d][mr + g + 8]     = O[nt].z * i1;
        Ps[d + 1][mr + g + 8] = O[nt].w * i1;
    }
    __syncthreads();
    {
        const int d = t >> 1;
        float* orow = &g_att[((size_t)b * DH_ + h * DV_ + d) * NN_];
        #pragma unroll
        for (int r = 0; r < 8; ++r) {
            const int qq = ((t & 1) * 8 + r) * 4;
            if (q0 + qq + 3 < NN_)
                *reinterpret_cast<float4*>(&orow[q0 + qq]) =
                    make_float4(Ps[d][qq], Ps[d][qq + 1], Ps[d][qq + 2], Ps[d][qq + 3]);
        }
    }
}

// =====================================================================
// launch
// =====================================================================
extern "C" void kernel_launch(void* const* d_in, const int* in_sizes, int n_in,
                              void* d_out, int out_size)
{
    const float* x      = (const float*)d_in[0];
    const float* qkv_w  = (const float*)d_in[1];
    const float* qkv_g  = (const float*)d_in[2];
    const float* qkv_b  = (const float*)d_in[3];
    const float* qkv_m  = (const float*)d_in[4];
    const float* qkv_v  = (const float*)d_in[5];
    const float* dw_w   = (const float*)d_in[6];
    const float* dw_g   = (const float*)d_in[7];
    const float* dw_b   = (const float*)d_in[8];
    const float* dw_m   = (const float*)d_in[9];
    const float* dw_v   = (const float*)d_in[10];
    const float* ab     = (const float*)d_in[11];
    const float* proj_w = (const float*)d_in[12];
    const float* proj_g = (const float*)d_in[13];
    const float* proj_b = (const float*)d_in[14];
    const float* proj_m = (const float*)d_in[15];
    const float* proj_v = (const float*)d_in[16];
    float* out = (float*)d_out;

    void *p_qkv, *p_att;
    cudaGetSymbolAddress(&p_qkv, g_qkv);
    cudaGetSymbolAddress(&p_att, g_att);

    // 1) QKV 1x1 conv + BN : [768,256] x [256,784] per batch
    gemm_tf32<false><<<dim3(QKVO_ / 64, NN_ / 112, BB_), 128>>>(
        qkv_w, x, (float*)p_qkv, qkv_g, qkv_b, qkv_m, qkv_v,
        QKVO_, NN_, DIM_);

    // 2) depthwise 3x3 + BN on q channels
    dwconv_kernel<<<BB_ * NHKD_, 256>>>(dw_w, dw_g, dw_b, dw_m, dw_v);

    // 3) attention
    attn_tf32<<<dim3((NN_ + 63) / 64, HEADS_, BB_), 128>>>(ab);

    // 4) relu + proj 1x1 + BN : [256,512] x [512,784] per batch
    gemm_tf32<true><<<dim3(DIM_ / 64, NN_ / 112, BB_), 128>>>(
        proj_w, (const float*)p_att, out, proj_g, proj_b, proj_m, proj_v,
        DIM_, NN_, DH_);
}

// round 3
// speedup vs baseline: 2.8099x; 1.5720x over previous
#include <cuda_runtime.h>
#include <cuda_bf16.h>
#include <math.h>

#define BB_   32
#define DIM_  256
#define HEADS_ 8
#define KD_   16
#define DV_   64
#define NHKD_ 128
#define DH_   512
#define QKVO_ 768
#define WW_   28
#define NN_   784
#define EPSBN 1e-5f
#define SCALE_ 0.25f

// ---------------- scratch ----------------
__device__ float g_qkv[(size_t)BB_ * QKVO_ * NN_];
__device__ float g_qdw[(size_t)BB_ * NHKD_ * NN_];
__device__ float g_att[(size_t)BB_ * DH_ * NN_];

// ---------------- helpers ----------------
__device__ __forceinline__ float f2tff(float f) {
    unsigned u; asm("cvt.rna.tf32.f32 %0, %1;" : "=r"(u) : "f"(f));
    return __uint_as_float(u);
}
__device__ __forceinline__ void mma8(float4& c, const float4& a, const float2& b) {
    asm volatile(
        "mma.sync.aligned.m16n8k8.row.col.f32.tf32.tf32.f32 "
        "{%0,%1,%2,%3},{%4,%5,%6,%7},{%8,%9},{%0,%1,%2,%3};"
        : "+f"(c.x), "+f"(c.y), "+f"(c.z), "+f"(c.w)
        : "r"(__float_as_uint(a.x)), "r"(__float_as_uint(a.y)),
          "r"(__float_as_uint(a.z)), "r"(__float_as_uint(a.w)),
          "r"(__float_as_uint(b.x)), "r"(__float_as_uint(b.y)));
}

// =====================================================================
// tf32 GEMM + BN, fragment-layout smem.
// Block tile 128(M) x 112(N) x 32(K), 256 threads (8 warps, 4x2 grid),
// warp tile 32x56. Requires M%128==0, N%112==0, K%32==0.
// =====================================================================
template<bool RELU_IN>
__global__ void __launch_bounds__(256, 2) gemm_tf32(
    const float* __restrict__ A,
    const float* __restrict__ Bb,
    float*       __restrict__ Cb,
    const float* __restrict__ gg, const float* __restrict__ bbp,
    const float* __restrict__ mmp, const float* __restrict__ vvp,
    int M, int N, int K)
{
    const int m0 = blockIdx.x * 128;
    const int n0 = blockIdx.y * 112;
    const int z  = blockIdx.z;
    const float* Bz = Bb + (size_t)z * K * N;
    float*       C  = Cb + (size_t)z * M * N;

    // fragment-layout smem (padded row strides: 132 / 66 floats)
    __shared__ float Af[32 * 132];   // row = mi*4+ks (mi 0..7), [lane][slot0..3]
    __shared__ float Bf[56 * 66];    // row = nt*4+ks (nt 0..13), [lane][slot0..1]

    const int t    = threadIdx.x;
    const int lane = t & 31, wid = t >> 5;
    const int g    = lane >> 2, tg = lane & 3;
    const int wm   = wid >> 1, wn = wid & 1;

    float4 acc[2][7];
    #pragma unroll
    for (int i = 0; i < 2; ++i)
        #pragma unroll
        for (int j = 0; j < 7; ++j) acc[i][j] = make_float4(0.f, 0.f, 0.f, 0.f);

    // constant load coords
    const int arow0 = t >> 3;        // +32*j
    const int ac4   = t & 7;

    for (int k0 = 0; k0 < K; k0 += 32) {
        // ---- global loads to regs ----
        float4 av[4];
        #pragma unroll
        for (int j = 0; j < 4; ++j)
            av[j] = *reinterpret_cast<const float4*>(
                &A[(size_t)(m0 + arow0 + 32 * j) * K + k0 + ac4 * 4]);
        float4 bv[4];
        int brow[4], bc4[4];
        #pragma unroll
        for (int j = 0; j < 4; ++j) {
            const int idx = t + 256 * j;
            if (idx < 896) {
                brow[j] = idx / 28; bc4[j] = idx % 28;
                bv[j] = *reinterpret_cast<const float4*>(
                    &Bz[(size_t)(k0 + brow[j]) * N + n0 + bc4[j] * 4]);
                if (RELU_IN) {
                    bv[j].x = fmaxf(bv[j].x, 0.f); bv[j].y = fmaxf(bv[j].y, 0.f);
                    bv[j].z = fmaxf(bv[j].z, 0.f); bv[j].w = fmaxf(bv[j].w, 0.f);
                }
            }
        }
        __syncthreads();
        // ---- scatter to fragment layout ----
        #pragma unroll
        for (int j = 0; j < 4; ++j) {
            const int row = arow0 + 32 * j;
            const int mi = row >> 4, rr = row & 15;
            const int g2 = rr & 7, half = rr >> 3;
            const float vals[4] = {av[j].x, av[j].y, av[j].z, av[j].w};
            #pragma unroll
            for (int e = 0; e < 4; ++e) {
                const int c = ac4 * 4 + e;
                const int ks = c >> 3, chalf = (c & 7) >> 2, tgw = c & 3;
                Af[(mi * 4 + ks) * 132 + (4 * g2 + tgw) * 4 + half + 2 * chalf] =
                    f2tff(vals[e]);
            }
        }
        #pragma unroll
        for (int j = 0; j < 4; ++j) {
            const int idx = t + 256 * j;
            if (idx < 896) {
                const int row = brow[j];
                const int ks = row >> 3, tgf = row & 7;
                const int tgw = tgf & 3, slot = tgf >> 2;
                const float vals[4] = {bv[j].x, bv[j].y, bv[j].z, bv[j].w};
                #pragma unroll
                for (int e = 0; e < 4; ++e) {
                    const int n = bc4[j] * 4 + e;
                    const int nt = n >> 3, g2 = n & 7;
                    Bf[(nt * 4 + ks) * 66 + (4 * g2 + tgw) * 2 + slot] = f2tff(vals[e]);
                }
            }
        }
        __syncthreads();

        // ---- mma ----
        #pragma unroll
        for (int ks = 0; ks < 4; ++ks) {
            float4 a0 = *reinterpret_cast<const float4*>(
                &Af[((wm * 2 + 0) * 4 + ks) * 132 + lane * 4]);
            float4 a1 = *reinterpret_cast<const float4*>(
                &Af[((wm * 2 + 1) * 4 + ks) * 132 + lane * 4]);
            #pragma unroll
            for (int nt = 0; nt < 7; ++nt) {
                float2 b = *reinterpret_cast<const float2*>(
                    &Bf[((wn * 7 + nt) * 4 + ks) * 66 + lane * 2]);
                mma8(acc[0][nt], a0, b);
                mma8(acc[1][nt], a1, b);
            }
        }
    }

    // ---- BN epilogue ----
    #pragma unroll
    for (int mt = 0; mt < 2; ++mt) {
        const int r0 = m0 + (wm * 2 + mt) * 16 + g;
        const int r1 = r0 + 8;
        const float s0 = gg[r0] * rsqrtf(vvp[r0] + EPSBN);
        const float t0 = bbp[r0] - mmp[r0] * s0;
        const float s1 = gg[r1] * rsqrtf(vvp[r1] + EPSBN);
        const float t1 = bbp[r1] - mmp[r1] * s1;
        #pragma unroll
        for (int nt = 0; nt < 7; ++nt) {
            const int c = n0 + wn * 56 + nt * 8 + tg * 2;
            float4 a = acc[mt][nt];
            *reinterpret_cast<float2*>(&C[(size_t)r0 * N + c]) =
                make_float2(a.x * s0 + t0, a.y * s0 + t0);
            *reinterpret_cast<float2*>(&C[(size_t)r1 * N + c]) =
                make_float2(a.z * s1 + t1, a.w * s1 + t1);
        }
    }
}

// =====================================================================
// Depthwise 3x3 + BN
// =====================================================================
__global__ void __launch_bounds__(256) dwconv_kernel(
    const float* __restrict__ dw_w,
    const float* __restrict__ gg, const float* __restrict__ bb,
    const float* __restrict__ mm, const float* __restrict__ vv)
{
    const int bc = blockIdx.x;
    const int b  = bc >> 7;
    const int c  = bc & 127;
    const int t  = threadIdx.x;

    __shared__ float tile[30][30];
    for (int i = t; i < 900; i += 256) (&tile[0][0])[i] = 0.f;
    __syncthreads();

    const float* in = &g_qkv[((size_t)b * QKVO_ + c) * NN_];
    for (int n = t; n < NN_; n += 256)
        tile[n / WW_ + 1][n % WW_ + 1] = in[n];
    __syncthreads();

    float wv[9];
    #pragma unroll
    for (int k = 0; k < 9; ++k) wv[k] = dw_w[c * 9 + k];
    const float s  = gg[c] * rsqrtf(vv[c] + EPSBN);
    const float tt = bb[c] - mm[c] * s;

    float* outp = &g_qdw[((size_t)b * NHKD_ + c) * NN_];
    for (int n = t; n < NN_; n += 256) {
        const int y = n / WW_, x = n % WW_;
        float a = 0.f;
        #pragma unroll
        for (int ky = 0; ky < 3; ++ky)
            #pragma unroll
            for (int kx = 0; kx < 3; ++kx)
                a = fmaf(tile[y + ky][x + kx], wv[ky * 3 + kx], a);
        outp[n] = a * s + tt;
    }
}

// =====================================================================
// Flash attention, tf32 mma, fragment-layout smem.
// Block: 112 queries (7 warps x 16q), key chunks of 56 (784 = 14*56,
// mask-free). Scale folded into Q.
// smem offsets (floats): Qf 0 (14*132), Kf 1848 (14*66), Vf 2772 (56*66),
// Pf 6468 (49*132), bias 12936 (784). Total 13720 floats = 54880 B.
// =====================================================================
#define QF_ 0
#define KF_ 1848
#define VF_ 2772
#define PF_ 6468
#define BIAS_ 12936
#define ATT_SMEM_ (13720 * 4)

__global__ void __launch_bounds__(224, 2) attn_tf32(const float* __restrict__ ab)
{
    extern __shared__ float sm[];
    __shared__ int nyS[56], nxS[56];

    const int qt = blockIdx.x, h = blockIdx.y, b = blockIdx.z;
    const int q0 = qt * 112;
    const int t = threadIdx.x, lane = t & 31, wid = t >> 5;
    const int g = lane >> 2, tg = lane & 3;

    for (int i = t; i < 784; i += 224) sm[BIAS_ + i] = ab[h * 784 + i];

    // ---- Q stage: [16 d][112 q], scaled, to A-frag layout ----
    {
        const int d = t / 14, c4 = t % 14;   // base: 16 x 14 float4 positions... (448 total, 2 per thread)
        #pragma unroll
        for (int j = 0; j < 2; ++j) {
            const int idx = t + 224 * j;
            const int dd = idx / 28, cc4 = idx % 28;
            float4 v = *reinterpret_cast<const float4*>(
                &g_qdw[((size_t)b * NHKD_ + h * KD_ + dd) * NN_ + q0 + cc4 * 4]);
            const int ks = dd >> 3, df = dd & 7;
            const int tgw = df & 3, chalf = df >> 2;
            const float vals[4] = {v.x, v.y, v.z, v.w};
            #pragma unroll
            for (int e = 0; e < 4; ++e) {
                const int ql = cc4 * 4 + e;
                const int mi = ql >> 4, rr = ql & 15;
                const int g2 = rr & 7, half = rr >> 3;
                sm[QF_ + (mi * 2 + ks) * 132 + (4 * g2 + tgw) * 4 + half + 2 * chalf] =
                    f2tff(vals[e] * SCALE_);
            }
        }
        (void)d; (void)c4;
    }

    // query coords for this thread's two rows
    const int qa = q0 + wid * 16 + g;
    const int qya = qa / WW_, qxa = qa % WW_;
    const int qyb = (qa + 8) / WW_, qxb = (qa + 8) % WW_;

    float M0 = -1e30f, M1 = -1e30f, L0 = 0.f, L1 = 0.f;
    float4 O[8];
    #pragma unroll
    for (int i = 0; i < 8; ++i) O[i] = make_float4(0.f, 0.f, 0.f, 0.f);

    const float* kbase = &g_qkv[((size_t)b * QKVO_ + NHKD_ + h * KD_) * NN_];
    const float* vbase = &g_qkv[((size_t)b * QKVO_ + 2 * NHKD_ + h * DV_) * NN_];

    for (int n0 = 0; n0 < NN_; n0 += 56) {
        __syncthreads();
        // ---- K chunk [16 d][56 n] -> B-frag (k-dim = d) ----
        {
            const int dd = t / 14, c4 = t % 14;   // 224 positions exactly
            float4 v = *reinterpret_cast<const float4*>(
                &kbase[(size_t)dd * NN_ + n0 + c4 * 4]);
            const int ks = dd >> 3, tgf = dd & 7;
            const int tgw = tgf & 3, slot = tgf >> 2;
            const float vals[4] = {v.x, v.y, v.z, v.w};
            #pragma unroll
            for (int e = 0; e < 4; ++e) {
                const int nl = c4 * 4 + e;
                const int nt = nl >> 3, g2 = nl & 7;
                sm[KF_ + (nt * 2 + ks) * 66 + (4 * g2 + tgw) * 2 + slot] = f2tff(vals[e]);
            }
        }
        // ---- V chunk [64 d][56 n] -> B-frag (k-dim = n) ----
        #pragma unroll
        for (int j = 0; j < 4; ++j) {
            const int idx = t + 224 * j;             // 896 positions
            const int dd = idx / 14, c4 = idx % 14;
            float4 v = *reinterpret_cast<const float4*>(
                &vbase[(size_t)dd * NN_ + n0 + c4 * 4]);
            const int nt = dd >> 3, g2 = dd & 7;
            const float vals[4] = {v.x, v.y, v.z, v.w};
            #pragma unroll
            for (int e = 0; e < 4; ++e) {
                const int nl = c4 * 4 + e;
                const int ks = nl >> 3, tgf = nl & 7;
                const int tgw = tgf & 3, slot = tgf >> 2;
                sm[VF_ + (nt * 7 + ks) * 66 + (4 * g2 + tgw) * 2 + slot] = f2tff(vals[e]);
            }
        }
        if (t < 56) {
            const int n = n0 + t;
            nyS[t] = n / WW_; nxS[t] = n % WW_;
        }
        __syncthreads();

        // ---- S = Qs . K  (16 x 56 per warp) ----
        float4 S[7];
        #pragma unroll
        for (int i = 0; i < 7; ++i) S[i] = make_float4(0.f, 0.f, 0.f, 0.f);
        #pragma unroll
        for (int ks = 0; ks < 2; ++ks) {
            float4 a = *reinterpret_cast<const float4*>(
                &sm[QF_ + (wid * 2 + ks) * 132 + lane * 4]);
            #pragma unroll
            for (int nt = 0; nt < 7; ++nt) {
                float2 bf = *reinterpret_cast<const float2*>(
                    &sm[KF_ + (nt * 2 + ks) * 66 + lane * 2]);
                mma8(S[nt], a, bf);
            }
        }

        // ---- bias ----
        #pragma unroll
        for (int nt = 0; nt < 7; ++nt) {
            const int c0 = nt * 8 + tg * 2;
            const int ny0 = nyS[c0], nx0 = nxS[c0];
            const int ny1 = nyS[c0 + 1], nx1 = nxS[c0 + 1];
            S[nt].x += sm[BIAS_ + abs(qya - ny0) * WW_ + abs(qxa - nx0)];
            S[nt].y += sm[BIAS_ + abs(qya - ny1) * WW_ + abs(qxa - nx1)];
            S[nt].z += sm[BIAS_ + abs(qyb - ny0) * WW_ + abs(qxb - nx0)];
            S[nt].w += sm[BIAS_ + abs(qyb - ny1) * WW_ + abs(qxb - nx1)];
        }

        // ---- online softmax (rows g, g+8) ----
        float mx0 = -1e30f, mx1 = -1e30f;
        #pragma unroll
        for (int nt = 0; nt < 7; ++nt) {
            mx0 = fmaxf(mx0, fmaxf(S[nt].x, S[nt].y));
            mx1 = fmaxf(mx1, fmaxf(S[nt].z, S[nt].w));
        }
        mx0 = fmaxf(mx0, __shfl_xor_sync(0xffffffffu, mx0, 1));
        mx0 = fmaxf(mx0, __shfl_xor_sync(0xffffffffu, mx0, 2));
        mx1 = fmaxf(mx1, __shfl_xor_sync(0xffffffffu, mx1, 1));
        mx1 = fmaxf(mx1, __shfl_xor_sync(0xffffffffu, mx1, 2));
        const float nM0 = fmaxf(M0, mx0), nM1 = fmaxf(M1, mx1);
        const float cor0 = __expf(M0 - nM0), cor1 = __expf(M1 - nM1);
        M0 = nM0; M1 = nM1;
        float rs0 = 0.f, rs1 = 0.f;
        #pragma unroll
        for (int nt = 0; nt < 7; ++nt) {
            S[nt].x = __expf(S[nt].x - nM0); rs0 += S[nt].x;
            S[nt].y = __expf(S[nt].y - nM0); rs0 += S[nt].y;
            S[nt].z = __expf(S[nt].z - nM1); rs1 += S[nt].z;
            S[nt].w = __expf(S[nt].w - nM1); rs1 += S[nt].w;
        }
        rs0 += __shfl_xor_sync(0xffffffffu, rs0, 1);
        rs0 += __shfl_xor_sync(0xffffffffu, rs0, 2);
        rs1 += __shfl_xor_sync(0xffffffffu, rs1, 1);
        rs1 += __shfl_xor_sync(0xffffffffu, rs1, 2);
        L0 = L0 * cor0 + rs0;
        L1 = L1 * cor1 + rs1;
        #pragma unroll
        for (int i = 0; i < 8; ++i) {
            O[i].x *= cor0; O[i].y *= cor0;
            O[i].z *= cor1; O[i].w *= cor1;
        }

        // ---- P to warp-private A-frag region ----
        #pragma unroll
        for (int nt = 0; nt < 7; ++nt) {
            const float pv[4] = {S[nt].x, S[nt].y, S[nt].z, S[nt].w};
            #pragma unroll
            for (int e = 0; e < 2; ++e) {
                const int cc = tg * 2 + e;             // col within 8-group
                const int chalf = cc >> 2, tgw = cc & 3;
                float* base = &sm[PF_ + (wid * 7 + nt) * 132 + (4 * g + tgw) * 4];
                base[0 + 2 * chalf] = f2tff(pv[e]);        // half 0 (row g)
                base[1 + 2 * chalf] = f2tff(pv[2 + e]);    // half 1 (row g+8)
            }
        }
        __syncwarp();

        // ---- O += P . V  (16 x 64 per warp) ----
        #pragma unroll
        for (int ks = 0; ks < 7; ++ks) {
            float4 a = *reinterpret_cast<const float4*>(
                &sm[PF_ + (wid * 7 + ks) * 132 + lane * 4]);
            #pragma unroll
            for (int nt = 0; nt < 8; ++nt) {
                float2 bf = *reinterpret_cast<const float2*>(
                    &sm[VF_ + (nt * 7 + ks) * 66 + lane * 2]);
                mma8(O[nt], a, bf);
            }
        }
    }

    // ---- normalize + store (direct, per-element) ----
    const float i0 = 1.f / L0, i1 = 1.f / L1;
    const size_t cbase = ((size_t)b * DH_ + h * DV_) * NN_;
    #pragma unroll
    for (int nt = 0; nt < 8; ++nt) {
        const int d0 = nt * 8 + tg * 2;
        g_att[cbase + (size_t)d0 * NN_ + qa]           = O[nt].x * i0;
        g_att[cbase + (size_t)(d0 + 1) * NN_ + qa]     = O[nt].y * i0;
        g_att[cbase + (size_t)d0 * NN_ + qa + 8]       = O[nt].z * i1;
        g_att[cbase + (size_t)(d0 + 1) * NN_ + qa + 8] = O[nt].w * i1;
    }
}

// =====================================================================
// launch
// =====================================================================
extern "C" void kernel_launch(void* const* d_in, const int* in_sizes, int n_in,
                              void* d_out, int out_size)
{
    const float* x      = (const float*)d_in[0];
    const float* qkv_w  = (const float*)d_in[1];
    const float* qkv_g  = (const float*)d_in[2];
    const float* qkv_b  = (const float*)d_in[3];
    const float* qkv_m  = (const float*)d_in[4];
    const float* qkv_v  = (const float*)d_in[5];
    const float* dw_w   = (const float*)d_in[6];
    const float* dw_g   = (const float*)d_in[7];
    const float* dw_b   = (const float*)d_in[8];
    const float* dw_m   = (const float*)d_in[9];
    const float* dw_v   = (const float*)d_in[10];
    const float* ab     = (const float*)d_in[11];
    const float* proj_w = (const float*)d_in[12];
    const float* proj_g = (const float*)d_in[13];
    const float* proj_b = (const float*)d_in[14];
    const float* proj_m = (const float*)d_in[15];
    const float* proj_v = (const float*)d_in[16];
    float* out = (float*)d_out;

    void *p_qkv, *p_att;
    cudaGetSymbolAddress(&p_qkv, g_qkv);
    cudaGetSymbolAddress(&p_att, g_att);

    static bool attr_done = false;
    if (!attr_done) {
        cudaFuncSetAttribute(attn_tf32,
                             cudaFuncAttributeMaxDynamicSharedMemorySize, ATT_SMEM_);
        attr_done = true;
    }

    // 1) QKV 1x1 + BN : [768,256] x [256,784] per batch
    gemm_tf32<false><<<dim3(QKVO_ / 128, NN_ / 112, BB_), 256>>>(
        qkv_w, x, (float*)p_qkv, qkv_g, qkv_b, qkv_m, qkv_v,
        QKVO_, NN_, DIM_);

    // 2) depthwise 3x3 + BN
    dwconv_kernel<<<BB_ * NHKD_, 256>>>(dw_w, dw_g, dw_b, dw_m, dw_v);

    // 3) attention
    attn_tf32<<<dim3(NN_ / 112, HEADS_, BB_), 224, ATT_SMEM_>>>(ab);

    // 4) relu + proj 1x1 + BN : [256,512] x [512,784] per batch
    gemm_tf32<true><<<dim3(DIM_ / 128, NN_ / 112, BB_), 256>>>(
        proj_w, (const float*)p_att, out, proj_g, proj_b, proj_m, proj_v,
        DIM_, NN_, DH_);
}

// round 4
// speedup vs baseline: 2.8213x; 1.0041x over previous
#include <cuda_runtime.h>
#include <cuda_bf16.h>
#include <math.h>

#define BB_   32
#define DIM_  256
#define HEADS_ 8
#define KD_   16
#define DV_   64
#define NHKD_ 128
#define DH_   512
#define QKVO_ 768
#define WW_   28
#define NN_   784
#define EPSBN 1e-5f
#define SCALE_ 0.25f
#define LOG2E_ 1.4426950408889634f

// ---------------- scratch ----------------
__device__ float g_qkv[(size_t)BB_ * QKVO_ * NN_];
__device__ float g_qdw[(size_t)BB_ * NHKD_ * NN_];
__device__ float g_att[(size_t)BB_ * DH_ * NN_];
__device__ float g_wqkv[QKVO_ * DIM_];   // prepacked fragment-layout weights
__device__ float g_wproj[DIM_ * DH_];

// ---------------- helpers ----------------
__device__ __forceinline__ float f2tff(float f) {
    unsigned u; asm("cvt.rna.tf32.f32 %0, %1;" : "=r"(u) : "f"(f));
    return __uint_as_float(u);
}
__device__ __forceinline__ float ex2f(float x) {
    float y; asm("ex2.approx.ftz.f32 %0, %1;" : "=f"(y) : "f"(x)); return y;
}
__device__ __forceinline__ void mma8(float4& c, const float4& a, const float2& b) {
    asm volatile(
        "mma.sync.aligned.m16n8k8.row.col.f32.tf32.tf32.f32 "
        "{%0,%1,%2,%3},{%4,%5,%6,%7},{%8,%9},{%0,%1,%2,%3};"
        : "+f"(c.x), "+f"(c.y), "+f"(c.z), "+f"(c.w)
        : "r"(__float_as_uint(a.x)), "r"(__float_as_uint(a.y)),
          "r"(__float_as_uint(a.z)), "r"(__float_as_uint(a.w)),
          "r"(__float_as_uint(b.x)), "r"(__float_as_uint(b.y)));
}

// =====================================================================
// Weight prepack: row-major [M,K] -> per-16x8-tile mma A-fragment layout,
// tf32-rounded. Tile (mi,ks): 32 lanes x float4.
// =====================================================================
__global__ void prepack_w(const float* __restrict__ W, float* __restrict__ P,
                          int M, int K)
{
    const int i = blockIdx.x * 256 + threadIdx.x;
    if (i >= M * K) return;
    const int m = i / K, k = i % K;
    const int mi = m >> 4, r = m & 15, g2 = r & 7, half = r >> 3;
    const int ks = k >> 3, kk = k & 7, tgw = kk & 3, kh = kk >> 2;
    P[((size_t)(mi * (K >> 3) + ks) * 32 + (g2 * 4 + tgw)) * 4 + half + 2 * kh] =
        f2tff(W[i]);
}

// =====================================================================
// tf32 GEMM + BN. A prepacked (global->reg fragments), B double-buffered
// fragment-layout smem, 1 sync / k-block.
// Block tile 128(M) x 112(N) x 32(K), 256 threads, warp tile 32x56.
// =====================================================================
template<bool RELU_IN, bool CVT_B, bool CVT_OUT>
__global__ void __launch_bounds__(256, 2) gemm_tf32(
    const float* __restrict__ Apk,
    const float* __restrict__ Bb,
    float*       __restrict__ Cb,
    const float* __restrict__ gg, const float* __restrict__ bbp,
    const float* __restrict__ mmp, const float* __restrict__ vvp,
    int M, int N, int K)
{
    const int n0 = blockIdx.y * 112;
    const int z  = blockIdx.z;
    const float* Bz = Bb + (size_t)z * K * N;
    float*       C  = Cb + (size_t)z * M * N;

    __shared__ float Bf[2][56 * 66];

    const int t    = threadIdx.x;
    const int lane = t & 31, wid = t >> 5;
    const int g    = lane >> 2, tg = lane & 3;
    const int wm   = wid >> 1, wn = wid & 1;
    const int nkt  = K >> 5;
    const int kd8  = K >> 3;

    float4 acc[2][7];
    #pragma unroll
    for (int i = 0; i < 2; ++i)
        #pragma unroll
        for (int j = 0; j < 7; ++j) acc[i][j] = make_float4(0.f, 0.f, 0.f, 0.f);

    // B load coords (constant per thread)
    int brow[4], bc4[4]; bool bok[4];
    #pragma unroll
    for (int j = 0; j < 4; ++j) {
        const int idx = t + 256 * j;
        bok[j] = idx < 896;
        brow[j] = bok[j] ? idx / 28 : 0;
        bc4[j]  = bok[j] ? idx % 28 : 0;
    }
    // B smem scatter targets (constant)
    int btgt[4][4];
    #pragma unroll
    for (int j = 0; j < 4; ++j) {
        const int ks = brow[j] >> 3, tgf = brow[j] & 7;
        const int tgw = tgf & 3, slot = tgf >> 2;
        #pragma unroll
        for (int e = 0; e < 4; ++e) {
            const int n = bc4[j] * 4 + e;
            btgt[j][e] = ((n >> 3) * 4 + ks) * 66 + ((n & 7) * 4 + tgw) * 2 + slot;
        }
    }

    float4 bv[4];
    auto loadB = [&](int kt) {
        #pragma unroll
        for (int j = 0; j < 4; ++j)
            if (bok[j]) {
                float4 v = *reinterpret_cast<const float4*>(
                    &Bz[(size_t)(kt * 32 + brow[j]) * N + n0 + bc4[j] * 4]);
                if (RELU_IN) {
                    v.x = fmaxf(v.x, 0.f); v.y = fmaxf(v.y, 0.f);
                    v.z = fmaxf(v.z, 0.f); v.w = fmaxf(v.w, 0.f);
                }
                bv[j] = v;
            }
    };
    auto stsB = [&](float* buf) {
        #pragma unroll
        for (int j = 0; j < 4; ++j)
            if (bok[j]) {
                const float vals[4] = {bv[j].x, bv[j].y, bv[j].z, bv[j].w};
                #pragma unroll
                for (int e = 0; e < 4; ++e)
                    buf[btgt[j][e]] = CVT_B ? f2tff(vals[e]) : vals[e];
            }
    };

    const int mi0 = blockIdx.x * 8 + wm * 2;   // warp's first 16-row tile

    loadB(0); stsB(Bf[0]);
    if (nkt > 1) loadB(1);

    for (int kt = 0; kt < nkt; ++kt) {
        // A fragments for this k-block: global -> regs (coalesced)
        float4 af[2][4];
        #pragma unroll
        for (int mt = 0; mt < 2; ++mt)
            #pragma unroll
            for (int ks = 0; ks < 4; ++ks)
                af[mt][ks] = *reinterpret_cast<const float4*>(
                    &Apk[((size_t)((mi0 + mt) * kd8 + kt * 4 + ks) * 32 + lane) * 4]);

        __syncthreads();
        if (kt + 1 < nkt) {
            stsB(Bf[(kt + 1) & 1]);
            if (kt + 2 < nkt) loadB(kt + 2);
        }

        const float* buf = Bf[kt & 1];
        #pragma unroll
        for (int ks = 0; ks < 4; ++ks) {
            #pragma unroll
            for (int nt = 0; nt < 7; ++nt) {
                float2 b = *reinterpret_cast<const float2*>(
                    &buf[((wn * 7 + nt) * 4 + ks) * 66 + lane * 2]);
                mma8(acc[0][nt], af[0][ks], b);
                mma8(acc[1][nt], af[1][ks], b);
            }
        }
    }

    // BN epilogue
    #pragma unroll
    for (int mt = 0; mt < 2; ++mt) {
        const int r0 = (mi0 + mt) * 16 + g;
        const int r1 = r0 + 8;
        const float s0 = gg[r0] * rsqrtf(vvp[r0] + EPSBN);
        const float t0 = bbp[r0] - mmp[r0] * s0;
        const float s1 = gg[r1] * rsqrtf(vvp[r1] + EPSBN);
        const float t1 = bbp[r1] - mmp[r1] * s1;
        #pragma unroll
        for (int nt = 0; nt < 7; ++nt) {
            const int c = n0 + wn * 56 + nt * 8 + tg * 2;
            float4 a = acc[mt][nt];
            float o00 = a.x * s0 + t0, o01 = a.y * s0 + t0;
            float o10 = a.z * s1 + t1, o11 = a.w * s1 + t1;
            if (CVT_OUT) { o00 = f2tff(o00); o01 = f2tff(o01);
                           o10 = f2tff(o10); o11 = f2tff(o11); }
            *reinterpret_cast<float2*>(&C[(size_t)r0 * N + c]) = make_float2(o00, o01);
            *reinterpret_cast<float2*>(&C[(size_t)r1 * N + c]) = make_float2(o10, o11);
        }
    }
}

// =====================================================================
// Depthwise 3x3 + BN, tf32-rounded output
// =====================================================================
__global__ void __launch_bounds__(256) dwconv_kernel(
    const float* __restrict__ dw_w,
    const float* __restrict__ gg, const float* __restrict__ bb,
    const float* __restrict__ mm, const float* __restrict__ vv)
{
    const int bc = blockIdx.x;
    const int b  = bc >> 7;
    const int c  = bc & 127;
    const int t  = threadIdx.x;

    __shared__ float tile[30][30];
    for (int i = t; i < 900; i += 256) (&tile[0][0])[i] = 0.f;
    __syncthreads();

    const float* in = &g_qkv[((size_t)b * QKVO_ + c) * NN_];
    for (int n = t; n < NN_; n += 256)
        tile[n / WW_ + 1][n % WW_ + 1] = in[n];
    __syncthreads();

    float wv[9];
    #pragma unroll
    for (int k = 0; k < 9; ++k) wv[k] = dw_w[c * 9 + k];
    const float s  = gg[c] * rsqrtf(vv[c] + EPSBN);
    const float tt = bb[c] - mm[c] * s;

    float* outp = &g_qdw[((size_t)b * NHKD_ + c) * NN_];
    for (int n = t; n < NN_; n += 256) {
        const int y = n / WW_, x = n % WW_;
        float a = 0.f;
        #pragma unroll
        for (int ky = 0; ky < 3; ++ky)
            #pragma unroll
            for (int kx = 0; kx < 3; ++kx)
                a = fmaf(tile[y + ky][x + kx], wv[ky * 3 + kx], a);
        outp[n] = f2tff(a * s + tt);
    }
}

// =====================================================================
// Flash attention, tf32 mma, double-buffered K/V, exp2-domain softmax.
// Block: 112 queries (7 warps x 16q), key chunks of 56 (= 2 image rows).
// smem (floats): QF 0 (14*132), KF 1848/2772 (14*66 x2),
// VF 3696/7392 (56*66 x2), PF 11088 (49*132), BIAS 17556 (784). Tot 18340.
// =====================================================================
#define QF_   0
#define KF0_  1848
#define KF1_  2772
#define VF0_  3696
#define VF1_  7392
#define PF_   11088
#define BIAS_ 17556
#define ATT_SMEM_ (18340 * 4)

__global__ void __launch_bounds__(224, 2) attn_tf32(const float* __restrict__ ab)
{
    extern __shared__ float sm[];

    const int qt = blockIdx.x, h = blockIdx.y, b = blockIdx.z;
    const int q0 = qt * 112;
    const int t = threadIdx.x, lane = t & 31, wid = t >> 5;
    const int g = lane >> 2, tg = lane & 3;

    for (int i = t; i < 784; i += 224) sm[BIAS_ + i] = ab[h * 784 + i] * LOG2E_;

    // ---- Q stage: (pre-rounded) * SCALE*LOG2E, re-round, A-frag layout ----
    {
        const float qs = SCALE_ * LOG2E_;
        #pragma unroll
        for (int j = 0; j < 2; ++j) {
            const int idx = t + 224 * j;                   // 448 exact
            const int dd = idx / 28, cc4 = idx % 28;
            float4 v = *reinterpret_cast<const float4*>(
                &g_qdw[((size_t)b * NHKD_ + h * KD_ + dd) * NN_ + q0 + cc4 * 4]);
            const int ks = dd >> 3, df = dd & 7;
            const int tgw = df & 3, chalf = df >> 2;
            const float vals[4] = {v.x, v.y, v.z, v.w};
            #pragma unroll
            for (int e = 0; e < 4; ++e) {
                const int ql = cc4 * 4 + e;
                const int mi = ql >> 4, rr = ql & 15;
                const int g2 = rr & 7, half = rr >> 3;
                sm[QF_ + (mi * 2 + ks) * 132 + (4 * g2 + tgw) * 4 + half + 2 * chalf] =
                    f2tff(vals[e] * qs);
            }
        }
    }

    const int qa = q0 + wid * 16 + g;
    const int qya = qa / WW_, qxa = qa % WW_;
    const int qyb = (qa + 8) / WW_, qxb = (qa + 8) % WW_;

    float M0 = -1e30f, M1 = -1e30f, L0 = 0.f, L1 = 0.f;
    float4 O[8];
    #pragma unroll
    for (int i = 0; i < 8; ++i) O[i] = make_float4(0.f, 0.f, 0.f, 0.f);

    const float* kbase = &g_qkv[((size_t)b * QKVO_ + NHKD_ + h * KD_) * NN_];
    const float* vbase = &g_qkv[((size_t)b * QKVO_ + 2 * NHKD_ + h * DV_) * NN_];

    // K staging coords (constant)
    const int kdd = t / 14, kc4 = t % 14;
    const int kks = kdd >> 3, ktgf = kdd & 7;
    const int ktgw = ktgf & 3, kslot = ktgf >> 2;
    int ktgt[4];
    #pragma unroll
    for (int e = 0; e < 4; ++e) {
        const int nl = kc4 * 4 + e;
        ktgt[e] = ((nl >> 3) * 2 + kks) * 66 + ((nl & 7) * 4 + ktgw) * 2 + kslot;
    }
    // V staging coords (constant)
    int vtgt[4][4], vdd[4], vc4[4];
    #pragma unroll
    for (int j = 0; j < 4; ++j) {
        const int idx = t + 224 * j;                       // 896 exact
        vdd[j] = idx / 14; vc4[j] = idx % 14;
        const int nt = vdd[j] >> 3, g2 = vdd[j] & 7;
        #pragma unroll
        for (int e = 0; e < 4; ++e) {
            const int nl = vc4[j] * 4 + e;
            const int ks = nl >> 3, tgf = nl & 7;
            vtgt[j][e] = (nt * 7 + ks) * 66 + (g2 * 4 + (tgf & 3)) * 2 + (tgf >> 2);
        }
    }

    float4 kreg, vreg[4];
    auto loadKV = [&](int c) {
        const int n0 = c * 56;
        kreg = *reinterpret_cast<const float4*>(&kbase[(size_t)kdd * NN_ + n0 + kc4 * 4]);
        #pragma unroll
        for (int j = 0; j < 4; ++j)
            vreg[j] = *reinterpret_cast<const float4*>(
                &vbase[(size_t)vdd[j] * NN_ + n0 + vc4[j] * 4]);
    };
    auto stsKV = [&](float* kb, float* vb) {
        const float kv[4] = {kreg.x, kreg.y, kreg.z, kreg.w};
        #pragma unroll
        for (int e = 0; e < 4; ++e) kb[ktgt[e]] = kv[e];
        #pragma unroll
        for (int j = 0; j < 4; ++j) {
            const float vv4[4] = {vreg[j].x, vreg[j].y, vreg[j].z, vreg[j].w};
            #pragma unroll
            for (int e = 0; e < 4; ++e) vb[vtgt[j][e]] = vv4[e];
        }
    };

    loadKV(0);
    stsKV(sm + KF0_, sm + VF0_);
    loadKV(1);
    __syncthreads();

    // Q fragments -> registers (S-mma A operand)
    float4 qf[2];
    qf[0] = *reinterpret_cast<const float4*>(&sm[QF_ + (wid * 2 + 0) * 132 + lane * 4]);
    qf[1] = *reinterpret_cast<const float4*>(&sm[QF_ + (wid * 2 + 1) * 132 + lane * 4]);

    for (int c = 0; c < 14; ++c) {
        if (c + 1 < 14) {
            stsKV(sm + ((c + 1) & 1 ? KF1_ : KF0_), sm + ((c + 1) & 1 ? VF1_ : VF0_));
            if (c + 2 < 14) loadKV(c + 2);
        }
        const float* Kb = sm + ((c & 1) ? KF1_ : KF0_);
        const float* Vb = sm + ((c & 1) ? VF1_ : VF0_);

        // ---- S = Q.K ----
        float4 S[7];
        #pragma unroll
        for (int i = 0; i < 7; ++i) S[i] = make_float4(0.f, 0.f, 0.f, 0.f);
        #pragma unroll
        for (int ks = 0; ks < 2; ++ks)
            #pragma unroll
            for (int nt = 0; nt < 7; ++nt) {
                float2 bf = *reinterpret_cast<const float2*>(
                    &Kb[(nt * 2 + ks) * 66 + lane * 2]);
                mma8(S[nt], qf[ks], bf);
            }

        // ---- bias (chunk = image rows 2c, 2c+1) ----
        const int ry0 = 2 * c, ry1 = 2 * c + 1;
        const int ba0 = abs(qya - ry0) * WW_, ba1 = abs(qya - ry1) * WW_;
        const int bb0 = abs(qyb - ry0) * WW_, bb1 = abs(qyb - ry1) * WW_;
        #pragma unroll
        for (int nt = 0; nt < 7; ++nt) {
            const int c0 = nt * 8 + tg * 2, c1 = c0 + 1;
            const int nx0 = (c0 < 28) ? c0 : c0 - 28;
            const int nx1 = (c1 < 28) ? c1 : c1 - 28;
            const bool r0b = c0 >= 28, r1b = c1 >= 28;
            S[nt].x += sm[BIAS_ + (r0b ? ba1 : ba0) + abs(qxa - nx0)];
            S[nt].y += sm[BIAS_ + (r1b ? ba1 : ba0) + abs(qxa - nx1)];
            S[nt].z += sm[BIAS_ + (r0b ? bb1 : bb0) + abs(qxb - nx0)];
            S[nt].w += sm[BIAS_ + (r1b ? bb1 : bb0) + abs(qxb - nx1)];
        }

        // ---- online softmax (log2 domain) ----
        float mx0 = -1e30f, mx1 = -1e30f;
        #pragma unroll
        for (int nt = 0; nt < 7; ++nt) {
            mx0 = fmaxf(mx0, fmaxf(S[nt].x, S[nt].y));
            mx1 = fmaxf(mx1, fmaxf(S[nt].z, S[nt].w));
        }
        mx0 = fmaxf(mx0, __shfl_xor_sync(0xffffffffu, mx0, 1));
        mx0 = fmaxf(mx0, __shfl_xor_sync(0xffffffffu, mx0, 2));
        mx1 = fmaxf(mx1, __shfl_xor_sync(0xffffffffu, mx1, 1));
        mx1 = fmaxf(mx1, __shfl_xor_sync(0xffffffffu, mx1, 2));
        const float nM0 = fmaxf(M0, mx0), nM1 = fmaxf(M1, mx1);
        const float cor0 = ex2f(M0 - nM0), cor1 = ex2f(M1 - nM1);
        M0 = nM0; M1 = nM1;
        float rs0 = 0.f, rs1 = 0.f;
        #pragma unroll
        for (int nt = 0; nt < 7; ++nt) {
            S[nt].x = ex2f(S[nt].x - nM0); rs0 += S[nt].x;
            S[nt].y = ex2f(S[nt].y - nM0); rs0 += S[nt].y;
            S[nt].z = ex2f(S[nt].z - nM1); rs1 += S[nt].z;
            S[nt].w = ex2f(S[nt].w - nM1); rs1 += S[nt].w;
        }
        rs0 += __shfl_xor_sync(0xffffffffu, rs0, 1);
        rs0 += __shfl_xor_sync(0xffffffffu, rs0, 2);
        rs1 += __shfl_xor_sync(0xffffffffu, rs1, 1);
        rs1 += __shfl_xor_sync(0xffffffffu, rs1, 2);
        L0 = L0 * cor0 + rs0;
        L1 = L1 * cor1 + rs1;
        #pragma unroll
        for (int i = 0; i < 8; ++i) {
            O[i].x *= cor0; O[i].y *= cor0;
            O[i].z *= cor1; O[i].w *= cor1;
        }

        // ---- P -> warp-private A-frag region ----
        #pragma unroll
        for (int nt = 0; nt < 7; ++nt) {
            const float pv[4] = {S[nt].x, S[nt].y, S[nt].z, S[nt].w};
            #pragma unroll
            for (int e = 0; e < 2; ++e) {
                const int cc = tg * 2 + e;
                const int chalf = cc >> 2, tgw = cc & 3;
                float* base = &sm[PF_ + (wid * 7 + nt) * 132 + (4 * g + tgw) * 4];
                base[0 + 2 * chalf] = f2tff(pv[e]);
                base[1 + 2 * chalf] = f2tff(pv[2 + e]);
            }
        }
        __syncwarp();

        // ---- O += P.V ----
        #pragma unroll
        for (int ks = 0; ks < 7; ++ks) {
            float4 a = *reinterpret_cast<const float4*>(
                &sm[PF_ + (wid * 7 + ks) * 132 + lane * 4]);
            #pragma unroll
            for (int nt = 0; nt < 8; ++nt) {
                float2 bf = *reinterpret_cast<const float2*>(
                    &Vb[(nt * 7 + ks) * 66 + lane * 2]);
                mma8(O[nt], a, bf);
            }
        }
        __syncthreads();
    }

    // ---- normalize + store (rounded for proj GEMM) ----
    const float i0 = 1.f / L0, i1 = 1.f / L1;
    const size_t cbase = ((size_t)b * DH_ + h * DV_) * NN_;
    #pragma unroll
    for (int nt = 0; nt < 8; ++nt) {
        const int d0 = nt * 8 + tg * 2;
        g_att[cbase + (size_t)d0 * NN_ + qa]           = f2tff(O[nt].x * i0);
        g_att[cbase + (size_t)(d0 + 1) * NN_ + qa]     = f2tff(O[nt].y * i0);
        g_att[cbase + (size_t)d0 * NN_ + qa + 8]       = f2tff(O[nt].z * i1);
        g_att[cbase + (size_t)(d0 + 1) * NN_ + qa + 8] = f2tff(O[nt].w * i1);
    }
}

// =====================================================================
// launch
// =====================================================================
extern "C" void kernel_launch(void* const* d_in, const int* in_sizes, int n_in,
                              void* d_out, int out_size)
{
    const float* x      = (const float*)d_in[0];
    const float* qkv_w  = (const float*)d_in[1];
    const float* qkv_g  = (const float*)d_in[2];
    const float* qkv_b  = (const float*)d_in[3];
    const float* qkv_m  = (const float*)d_in[4];
    const float* qkv_v  = (const float*)d_in[5];
    const float* dw_w   = (const float*)d_in[6];
    const float* dw_g   = (const float*)d_in[7];
    const float* dw_b   = (const float*)d_in[8];
    const float* dw_m   = (const float*)d_in[9];
    const float* dw_v   = (const float*)d_in[10];
    const float* ab     = (const float*)d_in[11];
    const float* proj_w = (const float*)d_in[12];
    const float* proj_g = (const float*)d_in[13];
    const float* proj_b = (const float*)d_in[14];
    const float* proj_m = (const float*)d_in[15];
    const float* proj_v = (const float*)d_in[16];
    float* out = (float*)d_out;

    void *p_qkv, *p_att, *p_wqkv, *p_wproj;
    cudaGetSymbolAddress(&p_qkv, g_qkv);
    cudaGetSymbolAddress(&p_att, g_att);
    cudaGetSymbolAddress(&p_wqkv, g_wqkv);
    cudaGetSymbolAddress(&p_wproj, g_wproj);

    cudaFuncSetAttribute(attn_tf32,
                         cudaFuncAttributeMaxDynamicSharedMemorySize, ATT_SMEM_);

    // 0) weight prepack (fragment layout, tf32-rounded)
    prepack_w<<<(QKVO_ * DIM_ + 255) / 256, 256>>>(qkv_w, (float*)p_wqkv, QKVO_, DIM_);
    prepack_w<<<(DIM_ * DH_ + 255) / 256, 256>>>(proj_w, (float*)p_wproj, DIM_, DH_);

    // 1) QKV 1x1 + BN (output tf32-rounded)
    gemm_tf32<false, true, true><<<dim3(QKVO_ / 128, NN_ / 112, BB_), 256>>>(
        (const float*)p_wqkv, x, (float*)p_qkv, qkv_g, qkv_b, qkv_m, qkv_v,
        QKVO_, NN_, DIM_);

    // 2) depthwise 3x3 + BN (output tf32-rounded)
    dwconv_kernel<<<BB_ * NHKD_, 256>>>(dw_w, dw_g, dw_b, dw_m, dw_v);

    // 3) attention (output tf32-rounded)
    attn_tf32<<<dim3(NN_ / 112, HEADS_, BB_), 224, ATT_SMEM_>>>(ab);

    // 4) relu + proj 1x1 + BN (final output, full fp32)
    gemm_tf32<true, false, false><<<dim3(DIM_ / 128, NN_ / 112, BB_), 256>>>(
        (const float*)p_wproj, (const float*)p_att, out, proj_g, proj_b, proj_m, proj_v,
        DIM_, NN_, DH_);
}

// round 5
// speedup vs baseline: 3.4743x; 1.2314x over previous
#include <cuda_runtime.h>
#include <cuda_fp16.h>
#include <math.h>

#define BB_   32
#define DIM_  256
#define HEADS_ 8
#define KD_   16
#define DV_   64
#define NHKD_ 128
#define DH_   512
#define QKVO_ 768
#define WW_   28
#define NN_   784
#define EPSBN 1e-5f
#define SCALE_ 0.25f
#define LOG2E_ 1.4426950408889634f

// ---------------- scratch (fp16 intermediates) ----------------
__device__ __half g_qkv[(size_t)BB_ * QKVO_ * NN_];
__device__ __half g_qdw[(size_t)BB_ * NHKD_ * NN_];
__device__ __half g_att[(size_t)BB_ * DH_ * NN_];
__device__ __half g_wqkv[QKVO_ * DIM_];
__device__ __half g_wproj[DIM_ * DH_];

// ---------------- helpers ----------------
__device__ __forceinline__ float ex2f(float x) {
    float y; asm("ex2.approx.ftz.f32 %0, %1;" : "=f"(y) : "f"(x)); return y;
}
__device__ __forceinline__ unsigned fh2(float lo, float hi) {
    __half2 h = __floats2half2_rn(lo, hi);
    return *reinterpret_cast<unsigned*>(&h);
}
__device__ __forceinline__ unsigned h2u(__half2 h) {
    return *reinterpret_cast<unsigned*>(&h);
}
__device__ __forceinline__ void mma16(float4& c, const uint4& a, unsigned b0, unsigned b1) {
    asm volatile(
        "mma.sync.aligned.m16n8k16.row.col.f32.f16.f16.f32 "
        "{%0,%1,%2,%3},{%4,%5,%6,%7},{%8,%9},{%0,%1,%2,%3};"
        : "+f"(c.x), "+f"(c.y), "+f"(c.z), "+f"(c.w)
        : "r"(a.x), "r"(a.y), "r"(a.z), "r"(a.w), "r"(b0), "r"(b1));
}

// =====================================================================
// Weight prepack: row-major fp32 [M,K] -> fp16 m16n8k16 A-fragment layout.
// uint4 per (tile mi,ks16; lane). reg = half + 2*kh, halfslot = k&1.
// =====================================================================
__global__ void prepack_w(const float* __restrict__ W, __half* __restrict__ P,
                          int M, int K)
{
    const int i = blockIdx.x * 256 + threadIdx.x;
    if (i >= M * K) return;
    const int m = i / K, k = i % K;
    const int mi = m >> 4, r = m & 15, g2 = r & 7, hf = r >> 3;
    const int ks = k >> 4, kk = k & 15;
    const int tgw = (kk >> 1) & 3, kh = kk >> 3, lo = kk & 1;
    P[((size_t)((mi * (K >> 4) + ks) * 32) + g2 * 4 + tgw) * 8 + (hf + 2 * kh) * 2 + lo]
        = __float2half_rn(W[i]);
}

// =====================================================================
// fp16 GEMM + BN. A prepacked (global->reg), B staged to B-frag smem,
// double-buffered. Block 128(M) x 112(N) x 32(K), 256 thr, warp 32x56.
// =====================================================================
template<bool B_HALF, bool OUT_HALF>
__global__ void __launch_bounds__(256, 2) gemm_f16(
    const uint4* __restrict__ Apk,
    const void*  __restrict__ Bsrc,
    void*        __restrict__ Cb,
    const float* __restrict__ gg, const float* __restrict__ bbp,
    const float* __restrict__ mmp, const float* __restrict__ vvp,
    int M, int N, int K)
{
    const int n0 = blockIdx.y * 112;
    const int z  = blockIdx.z;

    // uint idx = ((nt*32+lane)*2 + ks)*2 + kh  (14 nt, 2 ks, per k-block 32)
    __shared__ unsigned Bf[2][14 * 32 * 4];

    const int t    = threadIdx.x;
    const int lane = t & 31, wid = t >> 5;
    const int g    = lane >> 2, tg = lane & 3;
    const int wm   = wid >> 1, wn = wid & 1;
    const int nkt  = K >> 5;
    const int kt16 = K >> 4;

    float4 acc[2][7];
    #pragma unroll
    for (int i = 0; i < 2; ++i)
        #pragma unroll
        for (int j = 0; j < 7; ++j) acc[i][j] = make_float4(0.f, 0.f, 0.f, 0.f);

    // staging tasks: 448 = 16 k-pairs x 28 n4-groups
    int pj[2], n4j[2]; bool okj[2];
    int tgt[2][4];
    #pragma unroll
    for (int j = 0; j < 2; ++j) {
        const int idx = t + 256 * j;
        okj[j] = idx < 448;
        pj[j]  = okj[j] ? idx / 28 : 0;
        n4j[j] = okj[j] ? idx % 28 : 0;
        const int p = pj[j];
        #pragma unroll
        for (int e = 0; e < 4; ++e) {
            const int n = n4j[j] * 4 + e;
            tgt[j][e] = (((n >> 3) * 32 + (n & 7) * 4 + (p & 3)) * 2 + (p >> 3)) * 2
                        + ((p >> 2) & 1);
        }
    }

    unsigned uv[2][4];
    auto loadB = [&](int kt) {
        #pragma unroll
        for (int j = 0; j < 2; ++j) {
            if (!okj[j]) continue;
            const int k = kt * 32 + 2 * pj[j];
            const int nc = n0 + n4j[j] * 4;
            if (B_HALF) {
                const __half* Bh = (const __half*)Bsrc + (size_t)z * K * N;
                uint2 r0 = *reinterpret_cast<const uint2*>(&Bh[(size_t)k * N + nc]);
                uint2 r1 = *reinterpret_cast<const uint2*>(&Bh[(size_t)(k + 1) * N + nc]);
                __half2 A0 = *reinterpret_cast<__half2*>(&r0.x);
                __half2 A1 = *reinterpret_cast<__half2*>(&r0.y);
                __half2 B0 = *reinterpret_cast<__half2*>(&r1.x);
                __half2 B1 = *reinterpret_cast<__half2*>(&r1.y);
                uv[j][0] = h2u(__lows2half2(A0, B0));
                uv[j][1] = h2u(__highs2half2(A0, B0));
                uv[j][2] = h2u(__lows2half2(A1, B1));
                uv[j][3] = h2u(__highs2half2(A1, B1));
            } else {
                const float* Bff = (const float*)Bsrc + (size_t)z * K * N;
                float4 r0 = *reinterpret_cast<const float4*>(&Bff[(size_t)k * N + nc]);
                float4 r1 = *reinterpret_cast<const float4*>(&Bff[(size_t)(k + 1) * N + nc]);
                uv[j][0] = fh2(r0.x, r1.x);
                uv[j][1] = fh2(r0.y, r1.y);
                uv[j][2] = fh2(r0.z, r1.z);
                uv[j][3] = fh2(r0.w, r1.w);
            }
        }
    };
    auto stsB = [&](unsigned* buf) {
        #pragma unroll
        for (int j = 0; j < 2; ++j)
            if (okj[j]) {
                #pragma unroll
                for (int e = 0; e < 4; ++e) buf[tgt[j][e]] = uv[j][e];
            }
    };

    const int mi0 = blockIdx.x * 8 + wm * 2;

    loadB(0); stsB(Bf[0]);
    if (nkt > 1) loadB(1);

    for (int kt = 0; kt < nkt; ++kt) {
        uint4 af[2][2];
        #pragma unroll
        for (int mt = 0; mt < 2; ++mt)
            #pragma unroll
            for (int ks = 0; ks < 2; ++ks)
                af[mt][ks] = Apk[(size_t)((mi0 + mt) * kt16 + kt * 2 + ks) * 32 + lane];

        __syncthreads();
        if (kt + 1 < nkt) {
            stsB(Bf[(kt + 1) & 1]);
            if (kt + 2 < nkt) loadB(kt + 2);
        }

        const unsigned* buf = Bf[kt & 1];
        #pragma unroll
        for (int nt = 0; nt < 7; ++nt) {
            uint4 b4 = *reinterpret_cast<const uint4*>(
                &buf[((wn * 7 + nt) * 32 + lane) * 4]);
            mma16(acc[0][nt], af[0][0], b4.x, b4.y);
            mma16(acc[0][nt], af[0][1], b4.z, b4.w);
            mma16(acc[1][nt], af[1][0], b4.x, b4.y);
            mma16(acc[1][nt], af[1][1], b4.z, b4.w);
        }
    }

    // BN epilogue
    #pragma unroll
    for (int mt = 0; mt < 2; ++mt) {
        const int r0 = (mi0 + mt) * 16 + g;
        const int r1 = r0 + 8;
        const float s0 = gg[r0] * rsqrtf(vvp[r0] + EPSBN);
        const float t0 = bbp[r0] - mmp[r0] * s0;
        const float s1 = gg[r1] * rsqrtf(vvp[r1] + EPSBN);
        const float t1 = bbp[r1] - mmp[r1] * s1;
        #pragma unroll
        for (int nt = 0; nt < 7; ++nt) {
            const int c = n0 + wn * 56 + nt * 8 + tg * 2;
            float4 a = acc[mt][nt];
            if (OUT_HALF) {
                __half* C = (__half*)Cb + (size_t)z * M * N;
                *reinterpret_cast<unsigned*>(&C[(size_t)r0 * N + c]) =
                    fh2(a.x * s0 + t0, a.y * s0 + t0);
                *reinterpret_cast<unsigned*>(&C[(size_t)r1 * N + c]) =
                    fh2(a.z * s1 + t1, a.w * s1 + t1);
            } else {
                float* C = (float*)Cb + (size_t)z * M * N;
                *reinterpret_cast<float2*>(&C[(size_t)r0 * N + c]) =
                    make_float2(a.x * s0 + t0, a.y * s0 + t0);
                *reinterpret_cast<float2*>(&C[(size_t)r1 * N + c]) =
                    make_float2(a.z * s1 + t1, a.w * s1 + t1);
            }
        }
    }
}

// =====================================================================
// Depthwise 3x3 + BN; output scaled by SCALE*LOG2E (attention-ready), fp16
// =====================================================================
__global__ void __launch_bounds__(256) dwconv_kernel(
    const float* __restrict__ dw_w,
    const float* __restrict__ gg, const float* __restrict__ bb,
    const float* __restrict__ mm, const float* __restrict__ vv)
{
    const int bc = blockIdx.x;
    const int b  = bc >> 7;
    const int c  = bc & 127;
    const int t  = threadIdx.x;

    __shared__ float tile[30][30];
    for (int i = t; i < 900; i += 256) (&tile[0][0])[i] = 0.f;
    __syncthreads();

    const __half* in = &g_qkv[((size_t)b * QKVO_ + c) * NN_];
    for (int n = t; n < NN_; n += 256)
        tile[n / WW_ + 1][n % WW_ + 1] = __half2float(in[n]);
    __syncthreads();

    float wv[9];
    #pragma unroll
    for (int k = 0; k < 9; ++k) wv[k] = dw_w[c * 9 + k];
    const float s  = gg[c] * rsqrtf(vv[c] + EPSBN);
    const float tt = bb[c] - mm[c] * s;
    const float qs = SCALE_ * LOG2E_;

    __half* outp = &g_qdw[((size_t)b * NHKD_ + c) * NN_];
    for (int n = t; n < NN_; n += 256) {
        const int y = n / WW_, x = n % WW_;
        float a = 0.f;
        #pragma unroll
        for (int ky = 0; ky < 3; ++ky)
            #pragma unroll
            for (int kx = 0; kx < 3; ++kx)
                a = fmaf(tile[y + ky][x + kx], wv[ky * 3 + kx], a);
        outp[n] = __float2half_rn((a * s + tt) * qs);
    }
}

// =====================================================================
// Flash attention, fp16 m16n8k16. 112 queries (7 warps), chunks of 56 keys
// (mask-free), P kept entirely in registers (zero-padded to k=64),
// double-buffered K/V, exp2 softmax, relu folded into fp16 output.
// =====================================================================
__global__ void __launch_bounds__(224, 2) attn_f16(const float* __restrict__ ab)
{
    __shared__ unsigned Qf[7 * 32 * 4];        // A-frag: uint4 per (mi,lane)
    __shared__ unsigned Kf[2][7 * 32 * 2];     // B-frag: uint2 per (nt,lane)
    __shared__ unsigned Vf[2][8 * 32 * 8];     // ((nt*32+lane)*4+ks)*2+kh
    __shared__ float biasS[784];

    const int qt = blockIdx.x, h = blockIdx.y, b = blockIdx.z;
    const int q0 = qt * 112;
    const int t = threadIdx.x, lane = t & 31, wid = t >> 5;
    const int g = lane >> 2, tg = lane & 3;

    for (int i = t; i < 784; i += 224) biasS[i] = ab[h * 784 + i] * LOG2E_;

    // zero V k-pad (ks=3, kh=1) in both buffers; never written by staging
    for (int i = t; i < 512; i += 224) {
        const int bufi = i >> 8, r = i & 255;
        Vf[bufi][r * 8 + 7] = 0u;
    }

    // ---- Q staging (224 tasks exactly): rows d=2p,2p+1 at 4 queries ----
    {
        const int p = t / 28, q4 = t % 28;
        const __half* qrow = g_qdw + ((size_t)b * NHKD_ + h * KD_ + 2 * p) * NN_
                             + q0 + q4 * 4;
        uint2 r0 = *reinterpret_cast<const uint2*>(qrow);
        uint2 r1 = *reinterpret_cast<const uint2*>(qrow + NN_);
        __half2 A0 = *reinterpret_cast<__half2*>(&r0.x);
        __half2 A1 = *reinterpret_cast<__half2*>(&r0.y);
        __half2 B0 = *reinterpret_cast<__half2*>(&r1.x);
        __half2 B1 = *reinterpret_cast<__half2*>(&r1.y);
        unsigned u[4] = { h2u(__lows2half2(A0, B0)), h2u(__highs2half2(A0, B0)),
                          h2u(__lows2half2(A1, B1)), h2u(__highs2half2(A1, B1)) };
        #pragma unroll
        for (int e = 0; e < 4; ++e) {
            const int q = q4 * 4 + e;
            const int mi = q >> 4, r = q & 15;
            Qf[(mi * 32 + (r & 7) * 4 + (p & 3)) * 4 + ((r >> 3) + 2 * (p >> 2))] = u[e];
        }
    }

    const int qa = q0 + wid * 16 + g;
    const int qya = qa / WW_, qxa = qa % WW_;
    const int qyb = (qa + 8) / WW_, qxb = (qa + 8) % WW_;

    float M0 = -1e30f, M1 = -1e30f, L0 = 0.f, L1 = 0.f;
    float4 O[8];
    #pragma unroll
    for (int i = 0; i < 8; ++i) O[i] = make_float4(0.f, 0.f, 0.f, 0.f);

    const __half* kbase = &g_qkv[((size_t)b * QKVO_ + NHKD_ + h * KD_) * NN_];
    const __half* vbase = &g_qkv[((size_t)b * QKVO_ + 2 * NHKD_ + h * DV_) * NN_];

    // K staging: 112 tasks (t < 112): d-pair p, n4
    const bool kok = t < 112;
    const int kp = kok ? t / 14 : 0, kn4 = kok ? t % 14 : 0;
    // V staging: 896 tasks (4 per thread): row d, n4
    int vd[4], vn4[4];
    #pragma unroll
    for (int j = 0; j < 4; ++j) {
        const int idx = t + 224 * j;
        vd[j] = idx / 14; vn4[j] = idx % 14;
    }

    unsigned ku[4];
    uint2 vreg[4];
    auto loadKV = [&](int c) {
        const int n0c = c * 56;
        if (kok) {
            const __half* kr = kbase + (size_t)(2 * kp) * NN_ + n0c + kn4 * 4;
            uint2 r0 = *reinterpret_cast<const uint2*>(kr);
            uint2 r1 = *reinterpret_cast<const uint2*>(kr + NN_);
            __half2 A0 = *reinterpret_cast<__half2*>(&r0.x);
            __half2 A1 = *reinterpret_cast<__half2*>(&r0.y);
            __half2 B0 = *reinterpret_cast<__half2*>(&r1.x);
            __half2 B1 = *reinterpret_cast<__half2*>(&r1.y);
            ku[0] = h2u(__lows2half2(A0, B0));  ku[1] = h2u(__highs2half2(A0, B0));
            ku[2] = h2u(__lows2half2(A1, B1));  ku[3] = h2u(__highs2half2(A1, B1));
        }
        #pragma unroll
        for (int j = 0; j < 4; ++j)
            vreg[j] = *reinterpret_cast<const uint2*>(
                &vbase[(size_t)vd[j] * NN_ + n0c + vn4[j] * 4]);
    };
    auto stsKV = [&](unsigned* kb, unsigned* vb) {
        if (kok) {
            #pragma unroll
            for (int e = 0; e < 4; ++e) {
                const int n = kn4 * 4 + e;
                kb[((n >> 3) * 32 + (n & 7) * 4 + (kp & 3)) * 2 + (kp >> 2)] = ku[e];
            }
        }
        #pragma unroll
        for (int j = 0; j < 4; ++j) {
            const int nl0 = vn4[j] * 4;
            const int tg0 = (nl0 >> 1) & 3, kh = (nl0 >> 3) & 1, ks = nl0 >> 4;
            const int base = ((vd[j] >> 3) * 32 + (vd[j] & 7) * 4);
            vb[((base + tg0) * 4 + ks) * 2 + kh]     = vreg[j].x;
            vb[((base + tg0 + 1) * 4 + ks) * 2 + kh] = vreg[j].y;
        }
    };

    loadKV(0);
    stsKV(Kf[0], Vf[0]);
    loadKV(1);
    __syncthreads();

    const uint4 qfrag = *reinterpret_cast<const uint4*>(&Qf[(wid * 32 + lane) * 4]);

    for (int c = 0; c < 14; ++c) {
        if (c + 1 < 14) {
            stsKV(Kf[(c + 1) & 1], Vf[(c + 1) & 1]);
            if (c + 2 < 14) loadKV(c + 2);
        }
        const unsigned* Kb = Kf[c & 1];
        const unsigned* Vb = Vf[c & 1];

        // ---- S = Q.K : 7 mma (k16 exact) ----
        float4 S[7];
        #pragma unroll
        for (int i = 0; i < 7; ++i) S[i] = make_float4(0.f, 0.f, 0.f, 0.f);
        #pragma unroll
        for (int nt = 0; nt < 7; ++nt) {
            uint2 kb = *reinterpret_cast<const uint2*>(&Kb[(nt * 32 + lane) * 2]);
            mma16(S[nt], qfrag, kb.x, kb.y);
        }

        // ---- bias (chunk = image rows 2c, 2c+1) ----
        const int ry0 = 2 * c, ry1 = 2 * c + 1;
        const int ba0 = abs(qya - ry0) * WW_, ba1 = abs(qya - ry1) * WW_;
        const int bb0 = abs(qyb - ry0) * WW_, bb1 = abs(qyb - ry1) * WW_;
        #pragma unroll
        for (int nt = 0; nt < 7; ++nt) {
            const int c0 = nt * 8 + tg * 2, c1 = c0 + 1;
            const int nx0 = (c0 < 28) ? c0 : c0 - 28;
            const int nx1 = (c1 < 28) ? c1 : c1 - 28;
            const bool r0b = c0 >= 28, r1b = c1 >= 28;
            S[nt].x += biasS[(r0b ? ba1 : ba0) + abs(qxa - nx0)];
            S[nt].y += biasS[(r1b ? ba1 : ba0) + abs(qxa - nx1)];
            S[nt].z += biasS[(r0b ? bb1 : bb0) + abs(qxb - nx0)];
            S[nt].w += biasS[(r1b ? bb1 : bb0) + abs(qxb - nx1)];
        }

        // ---- online softmax (log2 domain) ----
        float mx0 = -1e30f, mx1 = -1e30f;
        #pragma unroll
        for (int nt = 0; nt < 7; ++nt) {
            mx0 = fmaxf(mx0, fmaxf(S[nt].x, S[nt].y));
            mx1 = fmaxf(mx1, fmaxf(S[nt].z, S[nt].w));
        }
        mx0 = fmaxf(mx0, __shfl_xor_sync(0xffffffffu, mx0, 1));
        mx0 = fmaxf(mx0, __shfl_xor_sync(0xffffffffu, mx0, 2));
        mx1 = fmaxf(mx1, __shfl_xor_sync(0xffffffffu, mx1, 1));
        mx1 = fmaxf(mx1, __shfl_xor_sync(0xffffffffu, mx1, 2));
        const float nM0 = fmaxf(M0, mx0), nM1 = fmaxf(M1, mx1);
        const float cor0 = ex2f(M0 - nM0), cor1 = ex2f(M1 - nM1);
        M0 = nM0; M1 = nM1;
        float rs0 = 0.f, rs1 = 0.f;
        #pragma unroll
        for (int nt = 0; nt < 7; ++nt) {
            S[nt].x = ex2f(S[nt].x - nM0); rs0 += S[nt].x;
            S[nt].y = ex2f(S[nt].y - nM0); rs0 += S[nt].y;
            S[nt].z = ex2f(S[nt].z - nM1); rs1 += S[nt].z;
            S[nt].w = ex2f(S[nt].w - nM1); rs1 += S[nt].w;
        }
        rs0 += __shfl_xor_sync(0xffffffffu, rs0, 1);
        rs0 += __shfl_xor_sync(0xffffffffu, rs0, 2);
        rs1 += __shfl_xor_sync(0xffffffffu, rs1, 1);
        rs1 += __shfl_xor_sync(0xffffffffu, rs1, 2);
        L0 = L0 * cor0 + rs0;
        L1 = L1 * cor1 + rs1;
        #pragma unroll
        for (int i = 0; i < 8; ++i) {
            O[i].x *= cor0; O[i].y *= cor0;
            O[i].z *= cor1; O[i].w *= cor1;
        }

        // ---- P: registers only (A-frag packing; ks=3 upper half = pad) ----
        uint4 Pk[4];
        #pragma unroll
        for (int ks = 0; ks < 3; ++ks)
            Pk[ks] = make_uint4(fh2(S[2 * ks].x,     S[2 * ks].y),
                                fh2(S[2 * ks].z,     S[2 * ks].w),
                                fh2(S[2 * ks + 1].x, S[2 * ks + 1].y),
                                fh2(S[2 * ks + 1].z, S[2 * ks + 1].w));
        Pk[3] = make_uint4(fh2(S[6].x, S[6].y), fh2(S[6].z, S[6].w), 0u, 0u);

        // ---- O += P.V : 32 mma ----
        #pragma unroll
        for (int nt = 0; nt < 8; ++nt) {
            const unsigned* vb = &Vb[(nt * 32 + lane) * 8];
            uint4 a4 = *reinterpret_cast<const uint4*>(vb);
            uint4 b4 = *reinterpret_cast<const uint4*>(vb + 4);
            mma16(O[nt], Pk[0], a4.x, a4.y);
            mma16(O[nt], Pk[1], a4.z, a4.w);
            mma16(O[nt], Pk[2], b4.x, b4.y);
            mma16(O[nt], Pk[3], b4.z, b4.w);
        }
        __syncthreads();
    }

    // ---- normalize + relu + fp16 store ----
    const float i0 = 1.f / L0, i1 = 1.f / L1;
    __half* obase = g_att + ((size_t)b * DH_ + h * DV_) * NN_;
    #pragma unroll
    for (int nt = 0; nt < 8; ++nt) {
        const int d0 = nt * 8 + tg * 2;
        obase[(size_t)d0 * NN_ + qa]           = __float2half_rn(fmaxf(O[nt].x * i0, 0.f));
        obase[(size_t)(d0 + 1) * NN_ + qa]     = __float2half_rn(fmaxf(O[nt].y * i0, 0.f));
        obase[(size_t)d0 * NN_ + qa + 8]       = __float2half_rn(fmaxf(O[nt].z * i1, 0.f));
        obase[(size_t)(d0 + 1) * NN_ + qa + 8] = __float2half_rn(fmaxf(O[nt].w * i1, 0.f));
    }
}

// =====================================================================
// launch
// =====================================================================
extern "C" void kernel_launch(void* const* d_in, const int* in_sizes, int n_in,
                              void* d_out, int out_size)
{
    const float* x      = (const float*)d_in[0];
    const float* qkv_w  = (const float*)d_in[1];
    const float* qkv_g  = (const float*)d_in[2];
    const float* qkv_b  = (const float*)d_in[3];
    const float* qkv_m  = (const float*)d_in[4];
    const float* qkv_v  = (const float*)d_in[5];
    const float* dw_w   = (const float*)d_in[6];
    const float* dw_g   = (const float*)d_in[7];
    const float* dw_b   = (const float*)d_in[8];
    const float* dw_m   = (const float*)d_in[9];
    const float* dw_v   = (const float*)d_in[10];
    const float* ab     = (const float*)d_in[11];
    const float* proj_w = (const float*)d_in[12];
    const float* proj_g = (const float*)d_in[13];
    const float* proj_b = (const float*)d_in[14];
    const float* proj_m = (const float*)d_in[15];
    const float* proj_v = (const float*)d_in[16];
    float* out = (float*)d_out;

    void *p_qkv, *p_att, *p_wqkv, *p_wproj;
    cudaGetSymbolAddress(&p_qkv, g_qkv);
    cudaGetSymbolAddress(&p_att, g_att);
    cudaGetSymbolAddress(&p_wqkv, g_wqkv);
    cudaGetSymbolAddress(&p_wproj, g_wproj);

    // 0) weight prepack (fp16 A-fragment layout)
    prepack_w<<<(QKVO_ * DIM_ + 255) / 256, 256>>>(qkv_w, (__half*)p_wqkv, QKVO_, DIM_);
    prepack_w<<<(DIM_ * DH_ + 255) / 256, 256>>>(proj_w, (__half*)p_wproj, DIM_, DH_);

    // 1) QKV 1x1 + BN : fp32 input -> fp16 out
    gemm_f16<false, true><<<dim3(QKVO_ / 128, NN_ / 112, BB_), 256>>>(
        (const uint4*)p_wqkv, x, p_qkv, qkv_g, qkv_b, qkv_m, qkv_v,
        QKVO_, NN_, DIM_);

    // 2) depthwise 3x3 + BN (scaled for attention)
    dwconv_kernel<<<BB_ * NHKD_, 256>>>(dw_w, dw_g, dw_b, dw_m, dw_v);

    // 3) attention (relu folded in, fp16 out)
    attn_f16<<<dim3(NN_ / 112, HEADS_, BB_), 224>>>(ab);

    // 4) proj 1x1 + BN : fp16 input -> fp32 out
    gemm_f16<true, false><<<dim3(DIM_ / 128, NN_ / 112, BB_), 256>>>(
        (const uint4*)p_wproj, p_att, out, proj_g, proj_b, proj_m, proj_v,
        DIM_, NN_, DH_);
}